// round 8
// baseline (speedup 1.0000x reference)
#include <cuda_runtime.h>
#include <math.h>

#define BB 8
#define CC 64
#define NN 1000
#define TT 24
#define RR 10
#define NT 24000     // NN*TT
#define CT 1536      // CC*TT
#define NCO 64000    // NN*CC

// ------------------------- scratch (device globals, no allocs) -------------
__device__ float g_x1t[BB*1024*CT];       // x1 transposed [b][n(pad 1024)][(c*T+t)], tf32-rounded
__device__ float g_g1[BB*NN*CT];          // Ag @ x1t      [b][n][(c*T+t)]
__device__ float g_s1a[BB*CC*RR];
__device__ float g_s2a[BB*RR*CC];
__device__ float g_att0[BB*CC*CC];
__device__ float g_s1g[BB*NN*RR];
__device__ float g_s2g[BB*RR*NN];
__device__ float g_Ag[BB*1024*1024];      // gated adjacency [b][n][m pad 1024], tf32-rounded
__device__ float g_s1t[BB*TT*RR];
__device__ float g_s2t[BB*RR*TT];
__device__ float g_attT[BB*TT*TT];
// transposed / fused weights
__device__ float g_a0W1T[RR*NT];
__device__ float g_gW1T[RR*CT];
__device__ float g_F1T[RR*NCO];           // fused gcnW . tatt_W1  [r][(n*64+c)]
__device__ float g_F2T[RR*NCO];           // fused gcnW . tatt_W2  [r][(n*64+c)]
__device__ float g_w1T[2*CC*CC];          // conv1 [tap][c][o]
__device__ float g_w2T[2*CC*CC];          // conv2 [tap][c][o]
__device__ float g_rT[CC*CC];             // res_w [c][o]

// ------------------------- f32x2 / misc helpers ----------------------------
__device__ __forceinline__ unsigned long long dup2(float v) {
    unsigned long long r; unsigned u = __float_as_uint(v);
    asm("mov.b64 %0, {%1, %1};" : "=l"(r) : "r"(u));
    return r;
}
__device__ __forceinline__ unsigned long long pack2(float lo, float hi) {
    unsigned long long r;
    asm("mov.b64 %0, {%1, %2};" : "=l"(r) : "r"(__float_as_uint(lo)), "r"(__float_as_uint(hi)));
    return r;
}
__device__ __forceinline__ void fma2(unsigned long long& d,
                                     unsigned long long a, unsigned long long b) {
    asm("fma.rn.f32x2 %0, %1, %2, %0;" : "+l"(d) : "l"(a), "l"(b));
}
__device__ __forceinline__ float lo32(unsigned long long v) {
    return __uint_as_float((unsigned)v);
}
__device__ __forceinline__ float hi32(unsigned long long v) {
    return __uint_as_float((unsigned)(v >> 32));
}
__device__ __forceinline__ float tf32r(float x) {
    unsigned u;
    asm("cvt.rna.tf32.f32 %0, %1;" : "=r"(u) : "f"(x));
    return __uint_as_float(u);
}
__device__ __forceinline__ unsigned smem_u32(const void* p) {
    unsigned a;
    asm("{ .reg .u64 t; cvta.to.shared.u64 t, %1; cvt.u32.u64 %0, t; }" : "=r"(a) : "l"(p));
    return a;
}
__device__ __forceinline__ void cpa16(unsigned dst, const void* src) {
    asm volatile("cp.async.ca.shared.global [%0], [%1], 16;" :: "r"(dst), "l"(src));
}
__device__ __forceinline__ void mma_tf32(float& c0, float& c1, float& c2, float& c3,
                                         unsigned a0, unsigned a1, unsigned a2, unsigned a3,
                                         unsigned b0, unsigned b1) {
    asm volatile("mma.sync.aligned.m16n8k8.row.col.f32.tf32.tf32.f32 "
                 "{%0,%1,%2,%3}, {%4,%5,%6,%7}, {%8,%9}, {%0,%1,%2,%3};"
                 : "+f"(c0), "+f"(c1), "+f"(c2), "+f"(c3)
                 : "r"(a0), "r"(a1), "r"(a2), "r"(a3), "r"(b0), "r"(b1));
}

// ------------------------- K0: weight prep + pad zero ----------------------
__global__ void k_prep(const float* __restrict__ a0W1, const float* __restrict__ gW1,
                       const float* __restrict__ c1w, const float* __restrict__ c2w,
                       const float* __restrict__ rw) {
    int e = blockIdx.x * 256 + threadIdx.x;
    if (e < NT*RR)  { int k = e/RR, r = e - k*RR; g_a0W1T[r*NT + k] = a0W1[e]; return; }
    e -= NT*RR;
    if (e < CT*RR)  { int k = e/RR, r = e - k*RR; g_gW1T[r*CT + k] = gW1[e]; return; }
    e -= CT*RR;
    if (e < CC*CC) {
        int o = e >> 6, c = e & 63;
        g_w1T[c*CC + o]         = c1w[e*2 + 0];
        g_w1T[CC*CC + c*CC + o] = c1w[e*2 + 1];
        g_w2T[c*CC + o]         = c2w[e*2 + 0];
        g_w2T[CC*CC + c*CC + o] = c2w[e*2 + 1];
        g_rT[c*CC + o]          = rw[e];
        return;
    }
    e -= CC*CC;
    if (e < BB*1024*24) {                      // zero A k-pad cols [1000,1024)
        int b = e / (1024*24); int rem = e - b*(1024*24);
        int row = rem / 24, col = 1000 + (rem - (rem/24)*24);
        g_Ag[((size_t)b*1024 + row)*1024 + col] = 0.f;
        return;
    }
    e -= BB*1024*24;
    if (e < BB*24*CT) {                        // zero x1t pad rows [1000,1024)
        int b = e / (24*CT); int rem = e - b*(24*CT);
        int row = 1000 + rem / CT, col = rem - (rem/CT)*CT;
        g_x1t[((size_t)b*1024 + row)*CT + col] = 0.f;
    }
}

// ------------------------- K0b: fuse gcn_W into tatt weights ---------------
__global__ void k_fuse(const float* __restrict__ gcnW, const float* __restrict__ tW1,
                       const float* __restrict__ tW2) {
    int n = blockIdx.x;
    __shared__ float gs[CC*CC];
    __shared__ float w1s[CC*RR];
    __shared__ float w2s[RR*CC];
    int tid = threadIdx.x;
    for (int e = tid; e < CC*CC; e += 256) gs[e] = gcnW[e];
    for (int e = tid; e < CC*RR; e += 256) w1s[e] = tW1[(size_t)(n*CC)*RR + e];
    for (int e = tid; e < RR*CC; e += 256) {
        int r = e / CC, o = e - r*CC;
        w2s[e] = tW2[(size_t)r*NCO + n*CC + o];
    }
    __syncthreads();
    for (int idx = tid; idx < CC*RR; idx += 256) {
        int c = idx / RR, r = idx - c*RR;
        float s1 = 0.f, s2 = 0.f;
#pragma unroll 16
        for (int o = 0; o < CC; o++) {
            float g = gs[c*CC + o];
            s1 += g * w1s[o*RR + r];
            s2 += g * w2s[r*CC + o];
        }
        g_F1T[(size_t)r*NCO + n*CC + c] = s1;
        g_F2T[(size_t)r*NCO + n*CC + c] = s2;
    }
}

// ------------------------- K1: channel-attn projections (4 rows/block) -----
__global__ void __launch_bounds__(256) k_attA_proj(const float* __restrict__ x,
                                                   const float* __restrict__ W2) {
    int g0 = blockIdx.x * 4;
    float a1[4][RR], a2[4][RR];
#pragma unroll
    for (int j = 0; j < 4; j++)
#pragma unroll
        for (int r = 0; r < RR; r++) { a1[j][r] = 0.f; a2[j][r] = 0.f; }
    for (int k4 = threadIdx.x * 4; k4 < NT; k4 += 1024) {
        float4 xv[4];
#pragma unroll
        for (int j = 0; j < 4; j++)
            xv[j] = *(const float4*)(x + (size_t)(g0 + j)*NT + k4);
#pragma unroll
        for (int r = 0; r < RR; r++) {
            float4 w1 = *(const float4*)(g_a0W1T + r*NT + k4);
            float4 w2 = *(const float4*)(W2 + r*NT + k4);
#pragma unroll
            for (int j = 0; j < 4; j++) {
                a1[j][r] += xv[j].x*w1.x + xv[j].y*w1.y + xv[j].z*w1.z + xv[j].w*w1.w;
                a2[j][r] += xv[j].x*w2.x + xv[j].y*w2.y + xv[j].z*w2.z + xv[j].w*w2.w;
            }
        }
    }
    __shared__ float red[8][80];
    int lane = threadIdx.x & 31, warp = threadIdx.x >> 5;
#pragma unroll
    for (int j = 0; j < 4; j++)
#pragma unroll
        for (int r = 0; r < RR; r++) {
#pragma unroll
            for (int off = 16; off > 0; off >>= 1) {
                a1[j][r] += __shfl_down_sync(0xffffffffu, a1[j][r], off);
                a2[j][r] += __shfl_down_sync(0xffffffffu, a2[j][r], off);
            }
            if (lane == 0) { red[warp][j*RR + r] = a1[j][r]; red[warp][40 + j*RR + r] = a2[j][r]; }
        }
    __syncthreads();
    int tid = threadIdx.x;
    if (tid < 80) {
        float s = 0.f;
#pragma unroll
        for (int w = 0; w < 8; w++) s += red[w][tid];
        if (tid < 40) {
            int j = tid / RR, r = tid - j*RR;
            g_s1a[(g0 + j)*RR + r] = s;
        } else {
            int k = tid - 40;
            int j = k / RR, r = k - j*RR;
            int bc = g0 + j, b = bc >> 6, c = bc & 63;
            g_s2a[(b*RR + r)*CC + c] = s;
        }
    }
}

// ------------------------- K2: channel-attn softmax (64x64) ----------------
__global__ void k_attA_soft() {
    int b = blockIdx.x >> 6, i = blockIdx.x & 63;
    int j = threadIdx.x;
    float s = 0.f;
#pragma unroll
    for (int r = 0; r < RR; r++) s += g_s1a[(b*CC + i)*RR + r] * g_s2a[(b*RR + r)*CC + j];
    s *= rsqrtf((float)NT);
    __shared__ float sm[CC];
    sm[j] = s; __syncthreads();
    float mx = -1e30f;
    for (int jj = 0; jj < CC; jj++) mx = fmaxf(mx, sm[jj]);
    float e = expf(s - mx);
    __syncthreads();
    sm[j] = e; __syncthreads();
    float sum = 0.f;
    for (int jj = 0; jj < CC; jj++) sum += sm[jj];
    g_att0[(b*CC + i)*CC + j] = e / sum;
}

// ------------------------- K3: x1t = att0 @ xf (tf32-rounded) --------------
__global__ void __launch_bounds__(256) k_chan_apply(const float* __restrict__ x) {
    int b = blockIdx.y;
    int k0 = blockIdx.x * 64;
    __shared__ float atts[CC][68];
    __shared__ float xfs[CC][64];
    int tid = threadIdx.x;
    for (int e = tid; e < CC*CC; e += 256) {
        int c = e >> 6, j = e & 63;
        atts[j][c] = g_att0[b*CC*CC + e];
    }
    for (int e = tid; e < CC*64; e += 256) {
        int j = e >> 6, kk = e & 63;
        xfs[j][kk] = x[(size_t)(b*CC + j)*NT + k0 + kk];
    }
    __syncthreads();
    int tx = tid & 15, ty = tid >> 4;
    unsigned long long acc[4][2];
#pragma unroll
    for (int i = 0; i < 4; i++) { acc[i][0] = 0ull; acc[i][1] = 0ull; }
#pragma unroll 4
    for (int j = 0; j < CC; j++) {
        float4 a = *(const float4*)&atts[j][ty*4];
        ulonglong2 xv = *(const ulonglong2*)&xfs[j][tx*4];
        unsigned long long d0 = dup2(a.x), d1 = dup2(a.y), d2 = dup2(a.z), d3 = dup2(a.w);
        fma2(acc[0][0], d0, xv.x); fma2(acc[0][1], d0, xv.y);
        fma2(acc[1][0], d1, xv.x); fma2(acc[1][1], d1, xv.y);
        fma2(acc[2][0], d2, xv.x); fma2(acc[2][1], d2, xv.y);
        fma2(acc[3][0], d3, xv.x); fma2(acc[3][1], d3, xv.y);
    }
    int nn[4], tt2[4];
#pragma unroll
    for (int ki = 0; ki < 4; ki++) {
        int kk = k0 + tx*4 + ki;
        nn[ki] = kk / TT;
        tt2[ki] = kk - nn[ki]*TT;
    }
#pragma unroll
    for (int ci = 0; ci < 4; ci++) {
        int c = ty*4 + ci;
        float v[4] = { lo32(acc[ci][0]), hi32(acc[ci][0]),
                       lo32(acc[ci][1]), hi32(acc[ci][1]) };
#pragma unroll
        for (int ki = 0; ki < 4; ki++)
            g_x1t[((size_t)b*1024 + nn[ki])*CT + c*TT + tt2[ki]] = tf32r(v[ki]);
    }
}

// ------------------------- K4: graph-attn projections (16 rows/block) ------
__global__ void __launch_bounds__(256) k_gatt_proj(const float* __restrict__ W2) {
    int base = blockIdx.x * 16;
    __shared__ float red[8][2*RR];
    int lane = threadIdx.x & 31, warp = threadIdx.x >> 5;
    for (int row = 0; row < 16; row++) {
        int bn = base + row;
        int b = bn / NN, n = bn - b*NN;
        const float* xf = g_x1t + ((size_t)b*1024 + n) * CT;
        float a1[RR], a2[RR];
#pragma unroll
        for (int r = 0; r < RR; r++) { a1[r] = 0.f; a2[r] = 0.f; }
        for (int k4 = threadIdx.x * 4; k4 < CT; k4 += 1024) {
            float4 xv = *(const float4*)(xf + k4);
#pragma unroll
            for (int r = 0; r < RR; r++) {
                float4 w1 = *(const float4*)(g_gW1T + r*CT + k4);
                float4 w2 = *(const float4*)(W2 + r*CT + k4);
                a1[r] += xv.x*w1.x + xv.y*w1.y + xv.z*w1.z + xv.w*w1.w;
                a2[r] += xv.x*w2.x + xv.y*w2.y + xv.z*w2.z + xv.w*w2.w;
            }
        }
#pragma unroll
        for (int r = 0; r < RR; r++) {
#pragma unroll
            for (int off = 16; off > 0; off >>= 1) {
                a1[r] += __shfl_down_sync(0xffffffffu, a1[r], off);
                a2[r] += __shfl_down_sync(0xffffffffu, a2[r], off);
            }
        }
        if (lane == 0) {
#pragma unroll
            for (int r = 0; r < RR; r++) { red[warp][r] = a1[r]; red[warp][RR+r] = a2[r]; }
        }
        __syncthreads();
        if (threadIdx.x < 2*RR) {
            float s = 0.f;
#pragma unroll
            for (int w = 0; w < 8; w++) s += red[w][threadIdx.x];
            if (threadIdx.x < RR) g_s1g[(size_t)bn*RR + threadIdx.x] = s;
            else                  g_s2g[((size_t)b*RR + (threadIdx.x - RR))*NN + n] = s;
        }
        __syncthreads();
    }
}

// ------------------------- K5: graph softmax * A_adj (tf32, padded) --------
__global__ void k_gatt_soft(const float* __restrict__ A_adj) {
    int bi = blockIdx.x;
    int b = bi / NN, i = bi - b*NN;
    __shared__ float sc[NN];
    __shared__ float s1r[RR];
    __shared__ float red[256];
    int tid = threadIdx.x;
    if (tid < RR) s1r[tid] = g_s1g[(size_t)(b*NN + i)*RR + tid];
    __syncthreads();
    float lmax = -1e30f;
    float scale = rsqrtf((float)CT);
    for (int j = tid; j < NN; j += 256) {
        float s = 0.f;
#pragma unroll
        for (int r = 0; r < RR; r++) s += s1r[r] * g_s2g[(size_t)(b*RR + r)*NN + j];
        s *= scale;
        sc[j] = s;
        lmax = fmaxf(lmax, s);
    }
    red[tid] = lmax; __syncthreads();
    for (int off = 128; off > 0; off >>= 1) {
        if (tid < off) red[tid] = fmaxf(red[tid], red[tid + off]);
        __syncthreads();
    }
    float mx = red[0];
    __syncthreads();
    float lsum = 0.f;
    for (int j = tid; j < NN; j += 256) {
        float e = expf(sc[j] - mx);
        sc[j] = e;
        lsum += e;
    }
    red[tid] = lsum; __syncthreads();
    for (int off = 128; off > 0; off >>= 1) {
        if (tid < off) red[tid] += red[tid + off];
        __syncthreads();
    }
    float inv = 1.f / red[0];
    for (int j = tid; j < NN; j += 256) {
        g_Ag[((size_t)b*1024 + i)*1024 + j] = tf32r(sc[j] * inv * A_adj[i*NN + j]);
    }
}

// ------------------------- K7: big GEMM via mma.sync tf32 ------------------
// C[128 x 128] per CTA. A = g_Ag [n][k pad1024], B = g_x1t [k pad1024 rows][j].
#define PA 36                   // A smem pitch (floats): banks 4g+tid4 distinct
#define PB 136                  // B smem pitch (floats): banks 8tid4+g distinct
#define ATILE (128*PA)          // 4608 floats
#define BTILE (32*PB)           // 4352 floats
#define GSM ((ATILE + BTILE) * 2 * 4)   // 71680 bytes

__global__ void __launch_bounds__(256) k_gemm_mma() {
    extern __shared__ float sm[];
    unsigned sbase = smem_u32(sm);
    int tid = threadIdx.x, warp = tid >> 5, lane = tid & 31;
    int b  = blockIdx.z;
    int n0 = blockIdx.y * 128;
    int j0 = blockIdx.x * 128;
    const float* Ab = g_Ag  + (size_t)b*1024*1024;
    const float* Bb = g_x1t + (size_t)b*1024*CT;

    // fill helper (lambda-free): chunk maps
    int a_row = tid >> 1, a_ci = (tid & 1) * 2;       // each thread: rows? -> use flat
    (void)a_row; (void)a_ci;

    float acc[4][4][4];
#pragma unroll
    for (int mi = 0; mi < 4; mi++)
#pragma unroll
        for (int ni = 0; ni < 4; ni++)
#pragma unroll
            for (int q = 0; q < 4; q++) acc[mi][ni][q] = 0.f;

    // prefetch tile 0
    {
        unsigned abase = sbase;
        unsigned bbase = sbase + ATILE*4;
#pragma unroll
        for (int i = 0; i < 4; i++) {
            int ch = tid + i*256;
            int row = ch >> 3, ci = ch & 7;
            cpa16(abase + (unsigned)(row*PA + ci*4)*4, Ab + (size_t)(n0 + row)*1024 + ci*4);
        }
#pragma unroll
        for (int i = 0; i < 4; i++) {
            int ch = tid + i*256;
            int row = ch >> 5, ci = ch & 31;
            cpa16(bbase + (unsigned)(row*PB + ci*4)*4, Bb + (size_t)row*CT + j0 + ci*4);
        }
        asm volatile("cp.async.commit_group;");
    }

    int g = lane >> 2, t4 = lane & 3;
    int wm = warp >> 2, wn = warp & 3;          // 2 m-warps x 4 n-warps

    for (int kt = 0; kt < 32; kt++) {
        int buf = kt & 1;
        if (kt < 31) {
            int k0 = (kt + 1) * 32;
            unsigned abase = sbase + (unsigned)((buf ^ 1) * (ATILE + BTILE)) * 4;
            unsigned bbase = abase + ATILE*4;
#pragma unroll
            for (int i = 0; i < 4; i++) {
                int ch = tid + i*256;
                int row = ch >> 3, ci = ch & 7;
                cpa16(abase + (unsigned)(row*PA + ci*4)*4,
                      Ab + (size_t)(n0 + row)*1024 + k0 + ci*4);
            }
#pragma unroll
            for (int i = 0; i < 4; i++) {
                int ch = tid + i*256;
                int row = ch >> 5, ci = ch & 31;
                cpa16(bbase + (unsigned)(row*PB + ci*4)*4,
                      Bb + (size_t)(k0 + row)*CT + j0 + ci*4);
            }
            asm volatile("cp.async.commit_group;");
            asm volatile("cp.async.wait_group 1;" ::: "memory");
        } else {
            asm volatile("cp.async.wait_group 0;" ::: "memory");
        }
        __syncthreads();
        const float* A_s = sm + buf * (ATILE + BTILE);
        const float* B_s = A_s + ATILE;
#pragma unroll
        for (int s = 0; s < 4; s++) {
            unsigned af[4][4];
#pragma unroll
            for (int mi = 0; mi < 4; mi++) {
                int m = wm*64 + mi*16;
                af[mi][0] = __float_as_uint(A_s[(m + g)*PA + s*8 + t4]);
                af[mi][1] = __float_as_uint(A_s[(m + g + 8)*PA + s*8 + t4]);
                af[mi][2] = __float_as_uint(A_s[(m + g)*PA + s*8 + t4 + 4]);
                af[mi][3] = __float_as_uint(A_s[(m + g + 8)*PA + s*8 + t4 + 4]);
            }
            unsigned bf[4][2];
#pragma unroll
            for (int ni = 0; ni < 4; ni++) {
                int j = wn*32 + ni*8;
                bf[ni][0] = __float_as_uint(B_s[(s*8 + t4)*PB + j + g]);
                bf[ni][1] = __float_as_uint(B_s[(s*8 + t4 + 4)*PB + j + g]);
            }
#pragma unroll
            for (int mi = 0; mi < 4; mi++)
#pragma unroll
                for (int ni = 0; ni < 4; ni++)
                    mma_tf32(acc[mi][ni][0], acc[mi][ni][1], acc[mi][ni][2], acc[mi][ni][3],
                             af[mi][0], af[mi][1], af[mi][2], af[mi][3],
                             bf[ni][0], bf[ni][1]);
        }
        __syncthreads();
    }

    // epilogue
#pragma unroll
    for (int mi = 0; mi < 4; mi++) {
        int r0 = n0 + wm*64 + mi*16 + g;
        int r1 = r0 + 8;
#pragma unroll
        for (int ni = 0; ni < 4; ni++) {
            int col = j0 + wn*32 + ni*8 + 2*t4;
            if (r0 < NN)
                *(float2*)&g_g1[((size_t)b*NN + r0)*CT + col] =
                    make_float2(acc[mi][ni][0], acc[mi][ni][1]);
            if (r1 < NN)
                *(float2*)&g_g1[((size_t)b*NN + r1)*CT + col] =
                    make_float2(acc[mi][ni][2], acc[mi][ni][3]);
        }
    }
}

// ------------------------- K8: temporal-attn projections (fused W, 4t) -----
__global__ void __launch_bounds__(256) k_tatt_proj() {
    int b  = blockIdx.x / 6;
    int tg = blockIdx.x - b*6;
    int t0 = tg * 4;
    const float* g1b = g_g1 + (size_t)b*NN*CT;
    unsigned long long a1p[2][RR], a2p[2][RR];
#pragma unroll
    for (int p = 0; p < 2; p++)
#pragma unroll
        for (int r = 0; r < RR; r++) { a1p[p][r] = 0ull; a2p[p][r] = 0ull; }

    for (int i4 = threadIdx.x * 4; i4 < NCO; i4 += 1024) {
        int n = i4 >> 6, c0 = i4 & 63;
        const float* gp = g1b + (size_t)n*CT + c0*TT + t0;
        unsigned long long gq[4][2];
#pragma unroll
        for (int j = 0; j < 4; j++) {
            ulonglong2 gv = *(const ulonglong2*)(gp + j*TT);
            gq[j][0] = gv.x; gq[j][1] = gv.y;
        }
#pragma unroll
        for (int r = 0; r < RR; r++) {
            float4 f1 = *(const float4*)(g_F1T + (size_t)r*NCO + i4);
            float4 f2 = *(const float4*)(g_F2T + (size_t)r*NCO + i4);
            unsigned long long d;
            d = dup2(f1.x); fma2(a1p[0][r], d, gq[0][0]); fma2(a1p[1][r], d, gq[0][1]);
            d = dup2(f1.y); fma2(a1p[0][r], d, gq[1][0]); fma2(a1p[1][r], d, gq[1][1]);
            d = dup2(f1.z); fma2(a1p[0][r], d, gq[2][0]); fma2(a1p[1][r], d, gq[2][1]);
            d = dup2(f1.w); fma2(a1p[0][r], d, gq[3][0]); fma2(a1p[1][r], d, gq[3][1]);
            d = dup2(f2.x); fma2(a2p[0][r], d, gq[0][0]); fma2(a2p[1][r], d, gq[0][1]);
            d = dup2(f2.y); fma2(a2p[0][r], d, gq[1][0]); fma2(a2p[1][r], d, gq[1][1]);
            d = dup2(f2.z); fma2(a2p[0][r], d, gq[2][0]); fma2(a2p[1][r], d, gq[2][1]);
            d = dup2(f2.w); fma2(a2p[0][r], d, gq[3][0]); fma2(a2p[1][r], d, gq[3][1]);
        }
    }
    __shared__ unsigned long long redu[8][40];
    int lane = threadIdx.x & 31, warp = threadIdx.x >> 5;
#pragma unroll
    for (int p = 0; p < 2; p++)
#pragma unroll
        for (int r = 0; r < RR; r++) {
            unsigned long long v1 = a1p[p][r], v2 = a2p[p][r];
#pragma unroll
            for (int off = 16; off > 0; off >>= 1) {
                float l1 = lo32(v1) + __shfl_down_sync(0xffffffffu, lo32(v1), off);
                float h1 = hi32(v1) + __shfl_down_sync(0xffffffffu, hi32(v1), off);
                float l2 = lo32(v2) + __shfl_down_sync(0xffffffffu, lo32(v2), off);
                float h2 = hi32(v2) + __shfl_down_sync(0xffffffffu, hi32(v2), off);
                v1 = pack2(l1, h1); v2 = pack2(l2, h2);
            }
            if (lane == 0) {
                redu[warp][r*2 + p]      = v1;
                redu[warp][20 + r*2 + p] = v2;
            }
        }
    __syncthreads();
    int tid = threadIdx.x;
    if (tid < 40) {
        float slo = 0.f, shi = 0.f;
#pragma unroll
        for (int w = 0; w < 8; w++) {
            unsigned long long v = redu[w][tid];
            slo += lo32(v); shi += hi32(v);
        }
        int mat = tid / 20;
        int rem = tid - mat*20;
        int r = rem >> 1, p = rem & 1;
        int t = t0 + 2*p;
        if (mat == 0) {
            g_s1t[(b*TT + t)*RR + r]     = slo;
            g_s1t[(b*TT + t + 1)*RR + r] = shi;
        } else {
            g_s2t[(b*RR + r)*TT + t]     = slo;
            g_s2t[(b*RR + r)*TT + t + 1] = shi;
        }
    }
}

// ------------------------- K9: temporal softmax (24x24) --------------------
__global__ void k_tatt_soft() {
    int b = blockIdx.x;
    int i = threadIdx.x;
    if (i >= TT) return;
    float sc[TT];
    float scale = rsqrtf((float)NCO);
#pragma unroll
    for (int j = 0; j < TT; j++) {
        float s = 0.f;
#pragma unroll
        for (int r = 0; r < RR; r++) s += g_s1t[(b*TT + i)*RR + r] * g_s2t[(b*RR + r)*TT + j];
        sc[j] = s * scale;
    }
    float mx = -1e30f;
#pragma unroll
    for (int j = 0; j < TT; j++) mx = fmaxf(mx, sc[j]);
    float sum = 0.f;
#pragma unroll
    for (int j = 0; j < TT; j++) { sc[j] = expf(sc[j] - mx); sum += sc[j]; }
    float inv = 1.f / sum;
#pragma unroll
    for (int j = 0; j < TT; j++) g_attT[(b*TT + i)*TT + j] = sc[j] * inv;
}

// ------------------------- K10: fused mix + tatt-apply + convs + res + LN --
__global__ void __launch_bounds__(256) k_final(
        const float* __restrict__ x,
        const float* __restrict__ gcnW,
        const float* __restrict__ c1b,
        const float* __restrict__ c2b,
        const float* __restrict__ rb,
        const float* __restrict__ lng,
        const float* __restrict__ lnb,
        float* __restrict__ out) {
    __shared__ float smB[4*CT];
    __shared__ float at_s[TT*TT];
    __shared__ float mu_s[4][TT], rs_s[4][TT];
    int blk = blockIdx.x;
    int b = blk / 250;
    int n0 = (blk - b*250) * 4;
    int tid = threadIdx.x;
    int u = tid >> 6, o = tid & 63;
    int n = n0 + u;

    {
        const float* src = g_g1 + ((size_t)b*NN + n0)*CT;
        for (int e4 = tid; e4 < CT; e4 += 256)
            *(float4*)&smB[e4*4] = *(const float4*)(src + e4*4);
    }
    for (int e = tid; e < TT*TT; e += 256) {
        int t = e / TT, tp = e - t*TT;
        at_s[tp*TT + t] = g_attT[b*TT*TT + e];
    }
    __syncthreads();

    unsigned long long gmp[12];
#pragma unroll
    for (int k = 0; k < 12; k++) gmp[k] = 0ull;
#pragma unroll 4
    for (int c = 0; c < CC; c++) {
        unsigned long long wd = dup2(__ldg(gcnW + c*CC + o));
        const unsigned long long* pr = (const unsigned long long*)&smB[u*CT + c*TT];
#pragma unroll
        for (int k = 0; k < 12; k++) fma2(gmp[k], wd, pr[k]);
    }
    float gm[TT];
#pragma unroll
    for (int k = 0; k < 12; k++) { gm[2*k] = lo32(gmp[k]); gm[2*k+1] = hi32(gmp[k]); }

    unsigned long long x2p[12];
#pragma unroll
    for (int k = 0; k < 12; k++) x2p[k] = 0ull;
#pragma unroll 4
    for (int tp = 0; tp < TT; tp++) {
        unsigned long long gd = dup2(gm[tp]);
        const unsigned long long* ar = (const unsigned long long*)&at_s[tp*TT];
#pragma unroll
        for (int k = 0; k < 12; k++) fma2(x2p[k], gd, ar[k]);
    }
    __syncthreads();
    {
        unsigned long long* wp = (unsigned long long*)&smB[u*CT + o*TT];
#pragma unroll
        for (int k = 0; k < 12; k++) wp[k] = x2p[k];
    }
    __syncthreads();

    unsigned long long yp[12];
    {
        unsigned long long bias = dup2(__ldg(c1b + o));
#pragma unroll
        for (int k = 0; k < 12; k++) yp[k] = bias;
#pragma unroll 4
        for (int c = 0; c < CC; c++) {
            const unsigned long long* pr = (const unsigned long long*)&smB[u*CT + c*TT];
            unsigned long long w0d = dup2(__ldg(g_w1T + c*CC + o));
            unsigned long long w1d = dup2(__ldg(g_w1T + CC*CC + c*CC + o));
            unsigned long long tp_[12];
#pragma unroll
            for (int k = 0; k < 12; k++) tp_[k] = pr[k];
#pragma unroll
            for (int k = 0; k < 12; k++) fma2(yp[k], w1d, tp_[k]);
            unsigned long long sh = pack2(0.f, lo32(tp_[0]));
            fma2(yp[0], w0d, sh);
#pragma unroll
            for (int k = 1; k < 12; k++) {
                sh = pack2(hi32(tp_[k-1]), lo32(tp_[k]));
                fma2(yp[k], w0d, sh);
            }
        }
    }
    float y1[TT];
#pragma unroll
    for (int k = 0; k < 12; k++) {
        y1[2*k]   = fmaxf(lo32(yp[k]), 0.f);
        y1[2*k+1] = fmaxf(hi32(yp[k]), 0.f);
    }
    __syncthreads();
    {
        float* wp = &smB[u*CT + o*TT];
#pragma unroll
        for (int k = 0; k < 6; k++)
            *(float4*)(wp + 4*k) = make_float4(y1[4*k], y1[4*k+1], y1[4*k+2], y1[4*k+3]);
    }
    __syncthreads();

    unsigned long long vp[12];
    {
        unsigned long long bias = dup2(__ldg(c2b + o));
#pragma unroll
        for (int k = 0; k < 12; k++) vp[k] = bias;
#pragma unroll 4
        for (int c = 0; c < CC; c++) {
            const unsigned long long* pr = (const unsigned long long*)&smB[u*CT + c*TT];
            unsigned long long w0d = dup2(__ldg(g_w2T + c*CC + o));
            unsigned long long w1d = dup2(__ldg(g_w2T + CC*CC + c*CC + o));
            unsigned long long prev = 0ull;
#pragma unroll
            for (int k = 0; k < 12; k++) {
                unsigned long long cur = pr[k];
                fma2(vp[k], w1d, cur);
                fma2(vp[k], w0d, prev);
                prev = cur;
            }
        }
    }
#pragma unroll
    for (int k = 0; k < 12; k++)
        vp[k] = pack2(fmaxf(lo32(vp[k]), 0.f), fmaxf(hi32(vp[k]), 0.f));
    __syncthreads();

    for (int e4 = tid; e4 < CT; e4 += 256) {
        int f = e4 * 4;
        int u2 = f / CT, rem = f - u2*CT;
        int c = rem / TT, t = rem - c*TT;
        *(float4*)&smB[f] = *(const float4*)(x + (size_t)((b*CC + c)*NN + n0 + u2)*TT + t);
    }
    __syncthreads();

#pragma unroll 4
    for (int c = 0; c < CC; c++) {
        const unsigned long long* pr = (const unsigned long long*)&smB[u*CT + c*TT];
        unsigned long long rwd = dup2(__ldg(g_rT + c*CC + o));
#pragma unroll
        for (int k = 0; k < 12; k++) fma2(vp[k], rwd, pr[k]);
    }
    {
        float biasr = __ldg(rb + o);
#pragma unroll
        for (int k = 0; k < 12; k++) {
            float lo = fmaxf(lo32(vp[k]) + biasr, 0.f);
            float hi = fmaxf(hi32(vp[k]) + biasr, 0.f);
            vp[k] = pack2(lo, hi);
        }
    }
    float v[TT];
#pragma unroll
    for (int k = 0; k < 12; k++) { v[2*k] = lo32(vp[k]); v[2*k+1] = hi32(vp[k]); }
    __syncthreads();

    {
        float* wp = &smB[u*CT + o*TT];
#pragma unroll
        for (int k = 0; k < 6; k++)
            *(float4*)(wp + 4*k) = make_float4(v[4*k], v[4*k+1], v[4*k+2], v[4*k+3]);
    }
    __syncthreads();
    if (tid < 96) {
        int ur = tid / TT, tr = tid - ur*TT;
        float S = 0.f, Q = 0.f;
#pragma unroll 8
        for (int oo = 0; oo < CC; oo++) {
            float val = smB[ur*CT + oo*TT + tr];
            S += val; Q += val*val;
        }
        float mu = S * (1.f/CC);
        float var = Q * (1.f/CC) - mu*mu;
        mu_s[ur][tr] = mu;
        rs_s[ur][tr] = rsqrtf(var + 1e-5f);
    }
    __syncthreads();
    {
        float gmul = __ldg(lng + o), badd = __ldg(lnb + o);
        float* op = out + (size_t)((b*CC + o)*NN + n)*TT;
        float res[TT];
#pragma unroll
        for (int t = 0; t < TT; t++)
            res[t] = (v[t] - mu_s[u][t]) * rs_s[u][t] * gmul + badd;
#pragma unroll
        for (int k = 0; k < 6; k++)
            *(float4*)(op + 4*k) = make_float4(res[4*k], res[4*k+1], res[4*k+2], res[4*k+3]);
    }
}

// ------------------------- launch ------------------------------------------
extern "C" void kernel_launch(void* const* d_in, const int* in_sizes, int n_in,
                              void* d_out, int out_size) {
    const float* x     = (const float*)d_in[0];
    const float* A_adj = (const float*)d_in[1];
    const float* a0W1  = (const float*)d_in[2];
    const float* a0W2  = (const float*)d_in[3];
    const float* gW1   = (const float*)d_in[4];
    const float* gW2   = (const float*)d_in[5];
    const float* gcnW  = (const float*)d_in[6];
    const float* tW1   = (const float*)d_in[7];
    const float* tW2   = (const float*)d_in[8];
    const float* c1w   = (const float*)d_in[9];
    const float* c1b   = (const float*)d_in[10];
    const float* c2w   = (const float*)d_in[11];
    const float* c2b   = (const float*)d_in[12];
    const float* resw  = (const float*)d_in[13];
    const float* resb  = (const float*)d_in[14];
    const float* lng   = (const float*)d_in[15];
    const float* lnb   = (const float*)d_in[16];
    float* out = (float*)d_out;

    cudaFuncSetAttribute(k_gemm_mma, cudaFuncAttributeMaxDynamicSharedMemorySize, GSM);

    // prep elems: NT*RR + CT*RR + CC*CC + A-pad + x1t-pad
    const int prep_elems = NT*RR + CT*RR + CC*CC + BB*1024*24 + BB*24*CT;
    k_prep<<<(prep_elems + 255)/256, 256>>>(a0W1, gW1, c1w, c2w, resw);
    k_fuse<<<NN, 256>>>(gcnW, tW1, tW2);
    k_attA_proj<<<BB*CC/4, 256>>>(x, a0W2);
    k_attA_soft<<<BB*CC, CC>>>();
    k_chan_apply<<<dim3(NT/64, BB), 256>>>(x);
    k_gatt_proj<<<BB*NN/16, 256>>>(gW2);
    k_gatt_soft<<<BB*NN, 256>>>(A_adj);
    k_gemm_mma<<<dim3(CT/128, 8, BB), 256, GSM>>>();
    k_tatt_proj<<<BB*6, 256>>>();
    k_tatt_soft<<<BB, 32>>>();
    k_final<<<BB*NN/4, 256>>>(x, gcnW, c1b, c2b, resb, lng, lnb, out);
}

// round 9
// speedup vs baseline: 1.0298x; 1.0298x over previous
#include <cuda_runtime.h>
#include <math.h>

#define BB 8
#define CC 64
#define NN 1000
#define TT 24
#define RR 10
#define NT 24000     // NN*TT
#define CT 1536      // CC*TT
#define NCO 64000    // NN*CC

// ------------------------- scratch (device globals, no allocs) -------------
__device__ float g_x1t[BB*NN*CT];         // x1 transposed [b][n][(c*T+t)]
__device__ float g_g1[BB*NN*CT];          // Ag @ x1t      [b][n][(c*T+t)]
__device__ float g_s1a[BB*CC*RR];
__device__ float g_s2a[BB*RR*CC];
__device__ float g_att0[BB*CC*CC];
__device__ float g_s1g[BB*NN*RR];
__device__ float g_s2g[BB*RR*NN];
__device__ float g_Ag[BB*NN*NN];          // gated adjacency [b,n,m]
__device__ float g_s1t[BB*TT*RR];
__device__ float g_s2t[BB*RR*TT];
__device__ float g_attT[BB*TT*TT];
// transposed / fused weights
__device__ float g_a0W1T[RR*NT];
__device__ float g_gW1T[RR*CT];
__device__ float g_F1T[RR*NCO];           // fused gcnW . tatt_W1  [r][(n*64+c)]
__device__ float g_F2T[RR*NCO];           // fused gcnW . tatt_W2  [r][(n*64+c)]
__device__ float g_w1T[2*CC*CC];          // conv1 [tap][c][o]
__device__ float g_w2T[2*CC*CC];          // conv2 [tap][c][o]
__device__ float g_rT[CC*CC];             // res_w [c][o]

// ------------------------- f32x2 helpers -----------------------------------
__device__ __forceinline__ unsigned long long dup2(float v) {
    unsigned long long r; unsigned u = __float_as_uint(v);
    asm("mov.b64 %0, {%1, %1};" : "=l"(r) : "r"(u));
    return r;
}
__device__ __forceinline__ unsigned long long pack2(float lo, float hi) {
    unsigned long long r;
    asm("mov.b64 %0, {%1, %2};" : "=l"(r) : "r"(__float_as_uint(lo)), "r"(__float_as_uint(hi)));
    return r;
}
__device__ __forceinline__ void fma2(unsigned long long& d,
                                     unsigned long long a, unsigned long long b) {
    asm("fma.rn.f32x2 %0, %1, %2, %0;" : "+l"(d) : "l"(a), "l"(b));
}
__device__ __forceinline__ float lo32(unsigned long long v) {
    return __uint_as_float((unsigned)v);
}
__device__ __forceinline__ float hi32(unsigned long long v) {
    return __uint_as_float((unsigned)(v >> 32));
}

// ------------------------- K0: weight prep (transposes) --------------------
__global__ void k_prep(const float* __restrict__ a0W1, const float* __restrict__ gW1,
                       const float* __restrict__ c1w, const float* __restrict__ c2w,
                       const float* __restrict__ rw) {
    int e = blockIdx.x * 256 + threadIdx.x;
    if (e < NT*RR)  { int k = e/RR, r = e - k*RR; g_a0W1T[r*NT + k] = a0W1[e]; return; }
    e -= NT*RR;
    if (e < CT*RR)  { int k = e/RR, r = e - k*RR; g_gW1T[r*CT + k] = gW1[e]; return; }
    e -= CT*RR;
    if (e < CC*CC) {
        int o = e >> 6, c = e & 63;
        g_w1T[c*CC + o]         = c1w[e*2 + 0];
        g_w1T[CC*CC + c*CC + o] = c1w[e*2 + 1];
        g_w2T[c*CC + o]         = c2w[e*2 + 0];
        g_w2T[CC*CC + c*CC + o] = c2w[e*2 + 1];
        g_rT[c*CC + o]          = rw[e];
    }
}

// ------------------------- K0b: fuse gcn_W into tatt weights ---------------
__global__ void k_fuse(const float* __restrict__ gcnW, const float* __restrict__ tW1,
                       const float* __restrict__ tW2) {
    int n = blockIdx.x;
    __shared__ float gs[CC*CC];
    __shared__ float w1s[CC*RR];
    __shared__ float w2s[RR*CC];
    int tid = threadIdx.x;
    for (int e = tid; e < CC*CC; e += 256) gs[e] = gcnW[e];
    for (int e = tid; e < CC*RR; e += 256) w1s[e] = tW1[(size_t)(n*CC)*RR + e];
    for (int e = tid; e < RR*CC; e += 256) {
        int r = e / CC, o = e - r*CC;
        w2s[e] = tW2[(size_t)r*NCO + n*CC + o];
    }
    __syncthreads();
    for (int idx = tid; idx < CC*RR; idx += 256) {
        int c = idx / RR, r = idx - c*RR;
        float s1 = 0.f, s2 = 0.f;
#pragma unroll 16
        for (int o = 0; o < CC; o++) {
            float g = gs[c*CC + o];
            s1 += g * w1s[o*RR + r];
            s2 += g * w2s[r*CC + o];
        }
        g_F1T[(size_t)r*NCO + n*CC + c] = s1;
        g_F2T[(size_t)r*NCO + n*CC + c] = s2;
    }
}

// ------------------------- K1: channel-attn projections (4 rows/block) -----
__global__ void __launch_bounds__(256) k_attA_proj(const float* __restrict__ x,
                                                   const float* __restrict__ W2) {
    int g0 = blockIdx.x * 4;
    float a1[4][RR], a2[4][RR];
#pragma unroll
    for (int j = 0; j < 4; j++)
#pragma unroll
        for (int r = 0; r < RR; r++) { a1[j][r] = 0.f; a2[j][r] = 0.f; }
    for (int k4 = threadIdx.x * 4; k4 < NT; k4 += 1024) {
        float4 xv[4];
#pragma unroll
        for (int j = 0; j < 4; j++)
            xv[j] = *(const float4*)(x + (size_t)(g0 + j)*NT + k4);
#pragma unroll
        for (int r = 0; r < RR; r++) {
            float4 w1 = *(const float4*)(g_a0W1T + r*NT + k4);
            float4 w2 = *(const float4*)(W2 + r*NT + k4);
#pragma unroll
            for (int j = 0; j < 4; j++) {
                a1[j][r] += xv[j].x*w1.x + xv[j].y*w1.y + xv[j].z*w1.z + xv[j].w*w1.w;
                a2[j][r] += xv[j].x*w2.x + xv[j].y*w2.y + xv[j].z*w2.z + xv[j].w*w2.w;
            }
        }
    }
    __shared__ float red[8][80];
    int lane = threadIdx.x & 31, warp = threadIdx.x >> 5;
#pragma unroll
    for (int j = 0; j < 4; j++)
#pragma unroll
        for (int r = 0; r < RR; r++) {
#pragma unroll
            for (int off = 16; off > 0; off >>= 1) {
                a1[j][r] += __shfl_down_sync(0xffffffffu, a1[j][r], off);
                a2[j][r] += __shfl_down_sync(0xffffffffu, a2[j][r], off);
            }
            if (lane == 0) { red[warp][j*RR + r] = a1[j][r]; red[warp][40 + j*RR + r] = a2[j][r]; }
        }
    __syncthreads();
    int tid = threadIdx.x;
    if (tid < 80) {
        float s = 0.f;
#pragma unroll
        for (int w = 0; w < 8; w++) s += red[w][tid];
        if (tid < 40) {
            int j = tid / RR, r = tid - j*RR;
            g_s1a[(g0 + j)*RR + r] = s;
        } else {
            int k = tid - 40;
            int j = k / RR, r = k - j*RR;
            int bc = g0 + j, b = bc >> 6, c = bc & 63;
            g_s2a[(b*RR + r)*CC + c] = s;
        }
    }
}

// ------------------------- K2: channel-attn softmax (64x64) ----------------
__global__ void k_attA_soft() {
    int b = blockIdx.x >> 6, i = blockIdx.x & 63;
    int j = threadIdx.x;
    float s = 0.f;
#pragma unroll
    for (int r = 0; r < RR; r++) s += g_s1a[(b*CC + i)*RR + r] * g_s2a[(b*RR + r)*CC + j];
    s *= rsqrtf((float)NT);
    __shared__ float sm[CC];
    sm[j] = s; __syncthreads();
    float mx = -1e30f;
    for (int jj = 0; jj < CC; jj++) mx = fmaxf(mx, sm[jj]);
    float e = expf(s - mx);
    __syncthreads();
    sm[j] = e; __syncthreads();
    float sum = 0.f;
    for (int jj = 0; jj < CC; jj++) sum += sm[jj];
    g_att0[(b*CC + i)*CC + j] = e / sum;
}

// ------------------------- K3: x1t = att0 @ xf (transposed out) ------------
__global__ void __launch_bounds__(256) k_chan_apply(const float* __restrict__ x) {
    int b = blockIdx.y;
    int k0 = blockIdx.x * 64;
    __shared__ float atts[CC][68];
    __shared__ float xfs[CC][64];
    int tid = threadIdx.x;
    for (int e = tid; e < CC*CC; e += 256) {
        int c = e >> 6, j = e & 63;
        atts[j][c] = g_att0[b*CC*CC + e];
    }
    for (int e = tid; e < CC*64; e += 256) {
        int j = e >> 6, kk = e & 63;
        xfs[j][kk] = x[(size_t)(b*CC + j)*NT + k0 + kk];
    }
    __syncthreads();
    int tx = tid & 15, ty = tid >> 4;
    unsigned long long acc[4][2];
#pragma unroll
    for (int i = 0; i < 4; i++) { acc[i][0] = 0ull; acc[i][1] = 0ull; }
#pragma unroll 4
    for (int j = 0; j < CC; j++) {
        float4 a = *(const float4*)&atts[j][ty*4];
        ulonglong2 xv = *(const ulonglong2*)&xfs[j][tx*4];
        unsigned long long d0 = dup2(a.x), d1 = dup2(a.y), d2 = dup2(a.z), d3 = dup2(a.w);
        fma2(acc[0][0], d0, xv.x); fma2(acc[0][1], d0, xv.y);
        fma2(acc[1][0], d1, xv.x); fma2(acc[1][1], d1, xv.y);
        fma2(acc[2][0], d2, xv.x); fma2(acc[2][1], d2, xv.y);
        fma2(acc[3][0], d3, xv.x); fma2(acc[3][1], d3, xv.y);
    }
    int nn[4], tt2[4];
#pragma unroll
    for (int ki = 0; ki < 4; ki++) {
        int kk = k0 + tx*4 + ki;
        nn[ki] = kk / TT;
        tt2[ki] = kk - nn[ki]*TT;
    }
#pragma unroll
    for (int ci = 0; ci < 4; ci++) {
        int c = ty*4 + ci;
        float v[4] = { lo32(acc[ci][0]), hi32(acc[ci][0]),
                       lo32(acc[ci][1]), hi32(acc[ci][1]) };
#pragma unroll
        for (int ki = 0; ki < 4; ki++)
            g_x1t[((size_t)b*NN + nn[ki])*CT + c*TT + tt2[ki]] = v[ki];
    }
}

// ------------------------- K4: graph-attn projections (16 rows/block) ------
__global__ void __launch_bounds__(256) k_gatt_proj(const float* __restrict__ W2) {
    int base = blockIdx.x * 16;
    __shared__ float red[8][2*RR];
    int lane = threadIdx.x & 31, warp = threadIdx.x >> 5;
    for (int row = 0; row < 16; row++) {
        int bn = base + row;
        int b = bn / NN, n = bn - b*NN;
        const float* xf = g_x1t + (size_t)bn * CT;
        float a1[RR], a2[RR];
#pragma unroll
        for (int r = 0; r < RR; r++) { a1[r] = 0.f; a2[r] = 0.f; }
        for (int k4 = threadIdx.x * 4; k4 < CT; k4 += 1024) {
            float4 xv = *(const float4*)(xf + k4);
#pragma unroll
            for (int r = 0; r < RR; r++) {
                float4 w1 = *(const float4*)(g_gW1T + r*CT + k4);
                float4 w2 = *(const float4*)(W2 + r*CT + k4);
                a1[r] += xv.x*w1.x + xv.y*w1.y + xv.z*w1.z + xv.w*w1.w;
                a2[r] += xv.x*w2.x + xv.y*w2.y + xv.z*w2.z + xv.w*w2.w;
            }
        }
#pragma unroll
        for (int r = 0; r < RR; r++) {
#pragma unroll
            for (int off = 16; off > 0; off >>= 1) {
                a1[r] += __shfl_down_sync(0xffffffffu, a1[r], off);
                a2[r] += __shfl_down_sync(0xffffffffu, a2[r], off);
            }
        }
        if (lane == 0) {
#pragma unroll
            for (int r = 0; r < RR; r++) { red[warp][r] = a1[r]; red[warp][RR+r] = a2[r]; }
        }
        __syncthreads();
        if (threadIdx.x < 2*RR) {
            float s = 0.f;
#pragma unroll
            for (int w = 0; w < 8; w++) s += red[w][threadIdx.x];
            if (threadIdx.x < RR) g_s1g[(size_t)bn*RR + threadIdx.x] = s;
            else                  g_s2g[((size_t)b*RR + (threadIdx.x - RR))*NN + n] = s;
        }
        __syncthreads();
    }
}

// ------------------------- K5: graph softmax * A_adj -----------------------
__global__ void k_gatt_soft(const float* __restrict__ A_adj) {
    int bi = blockIdx.x;
    int b = bi / NN, i = bi - b*NN;
    __shared__ float sc[NN];
    __shared__ float s1r[RR];
    __shared__ float red[256];
    int tid = threadIdx.x;
    if (tid < RR) s1r[tid] = g_s1g[(size_t)(b*NN + i)*RR + tid];
    __syncthreads();
    float lmax = -1e30f;
    float scale = rsqrtf((float)CT);
    for (int j = tid; j < NN; j += 256) {
        float s = 0.f;
#pragma unroll
        for (int r = 0; r < RR; r++) s += s1r[r] * g_s2g[(size_t)(b*RR + r)*NN + j];
        s *= scale;
        sc[j] = s;
        lmax = fmaxf(lmax, s);
    }
    red[tid] = lmax; __syncthreads();
    for (int off = 128; off > 0; off >>= 1) {
        if (tid < off) red[tid] = fmaxf(red[tid], red[tid + off]);
        __syncthreads();
    }
    float mx = red[0];
    __syncthreads();
    float lsum = 0.f;
    for (int j = tid; j < NN; j += 256) {
        float e = expf(sc[j] - mx);
        sc[j] = e;
        lsum += e;
    }
    red[tid] = lsum; __syncthreads();
    for (int off = 128; off > 0; off >>= 1) {
        if (tid < off) red[tid] += red[tid + off];
        __syncthreads();
    }
    float inv = 1.f / red[0];
    for (int j = tid; j < NN; j += 256) {
        g_Ag[((size_t)b*NN + i)*NN + j] = sc[j] * inv * A_adj[i*NN + j];
    }
}

// ------------------------- K7: big GEMM g1 = Ag @ x1t (f32x2) --------------
// double-buffered smem, ONE sync per k-tile, 2 CTAs/SM.
#define GTM 128
#define GTN 128
#define GTK 16
__global__ void __launch_bounds__(256, 2) k_gemm() {
    int b  = blockIdx.z;
    int n0 = blockIdx.y * GTM;
    int j0 = blockIdx.x * GTN;
    const float* A  = g_Ag  + (size_t)b*NN*NN;
    const float* Bm = g_x1t + (size_t)b*NN*CT;
    float*       Cm = g_g1  + (size_t)b*NN*CT;
    __shared__ float As[2][GTK][GTM + 4];
    __shared__ float Bs[2][GTK][GTN + 4];
    int tid = threadIdx.x;                     // 256
    int tx = tid & 15;
    int ty = tid >> 4;
    int an = tid >> 1, ah = (tid & 1) * 8;
    int bk = tid >> 4, bj = (tid & 15) * 8;
    const float4 z4 = make_float4(0.f, 0.f, 0.f, 0.f);

    unsigned long long acc[8][4];
#pragma unroll
    for (int i = 0; i < 8; i++)
#pragma unroll
        for (int j = 0; j < 4; j++) acc[i][j] = 0ull;

    const int NKT = (NN + GTK - 1) / GTK;      // 63
    // load tile 0 into buffer 0
    {
        int n = n0 + an;
        bool va = (n < NN) && (ah < NN);
        const float* pA = A + (size_t)n*NN + ah;
        float4 a0 = va ? *(const float4*)pA : z4;
        float4 a1 = va ? *(const float4*)(pA + 4) : z4;
        As[0][ah + 0][an] = a0.x; As[0][ah + 1][an] = a0.y;
        As[0][ah + 2][an] = a0.z; As[0][ah + 3][an] = a0.w;
        As[0][ah + 4][an] = a1.x; As[0][ah + 5][an] = a1.y;
        As[0][ah + 6][an] = a1.z; As[0][ah + 7][an] = a1.w;
        const float* pB = Bm + (size_t)bk*CT + j0 + bj;
        *(float4*)&Bs[0][bk][bj]     = *(const float4*)pB;
        *(float4*)&Bs[0][bk][bj + 4] = *(const float4*)(pB + 4);
    }
    __syncthreads();

    for (int kt = 0; kt < NKT; kt++) {
        int buf = kt & 1;
        float4 pa0, pa1, pb0, pb1;
        bool have_next = (kt + 1 < NKT);
        if (have_next) {
            int k0 = (kt + 1) * GTK;
            int n = n0 + an;
            bool va = (n < NN) && (k0 + ah < NN);
            const float* pA = A + (size_t)n*NN + k0 + ah;
            pa0 = va ? *(const float4*)pA : z4;
            pa1 = va ? *(const float4*)(pA + 4) : z4;
            bool vb = (k0 + bk < NN);
            const float* pB = Bm + (size_t)(k0 + bk)*CT + j0 + bj;
            pb0 = vb ? *(const float4*)pB : z4;
            pb1 = vb ? *(const float4*)(pB + 4) : z4;
        }
#pragma unroll
        for (int kk = 0; kk < GTK; kk++) {
            float4 a0 = *(const float4*)&As[buf][kk][ty*8];
            float4 a1 = *(const float4*)&As[buf][kk][ty*8 + 4];
            ulonglong2 b0 = *(const ulonglong2*)&Bs[buf][kk][tx*8];
            ulonglong2 b1 = *(const ulonglong2*)&Bs[buf][kk][tx*8 + 4];
            unsigned long long ad[8];
            ad[0] = dup2(a0.x); ad[1] = dup2(a0.y); ad[2] = dup2(a0.z); ad[3] = dup2(a0.w);
            ad[4] = dup2(a1.x); ad[5] = dup2(a1.y); ad[6] = dup2(a1.z); ad[7] = dup2(a1.w);
#pragma unroll
            for (int i = 0; i < 8; i++) {
                fma2(acc[i][0], ad[i], b0.x);
                fma2(acc[i][1], ad[i], b0.y);
                fma2(acc[i][2], ad[i], b1.x);
                fma2(acc[i][3], ad[i], b1.y);
            }
        }
        if (have_next) {
            int nb = buf ^ 1;
            As[nb][ah + 0][an] = pa0.x; As[nb][ah + 1][an] = pa0.y;
            As[nb][ah + 2][an] = pa0.z; As[nb][ah + 3][an] = pa0.w;
            As[nb][ah + 4][an] = pa1.x; As[nb][ah + 5][an] = pa1.y;
            As[nb][ah + 6][an] = pa1.z; As[nb][ah + 7][an] = pa1.w;
            *(float4*)&Bs[nb][bk][bj]     = pb0;
            *(float4*)&Bs[nb][bk][bj + 4] = pb1;
        }
        __syncthreads();
    }
#pragma unroll
    for (int i = 0; i < 8; i++) {
        int n = n0 + ty*8 + i;
        if (n < NN) {
            float* cp = Cm + (size_t)n*CT + j0 + tx*8;
            float4 v0 = make_float4(lo32(acc[i][0]), hi32(acc[i][0]),
                                    lo32(acc[i][1]), hi32(acc[i][1]));
            float4 v1 = make_float4(lo32(acc[i][2]), hi32(acc[i][2]),
                                    lo32(acc[i][3]), hi32(acc[i][3]));
            *(float4*)cp = v0;
            *(float4*)(cp + 4) = v1;
        }
    }
}

// ------------------------- K8: temporal-attn projections (fused W, 4t) -----
__global__ void __launch_bounds__(256) k_tatt_proj() {
    int b  = blockIdx.x / 6;
    int tg = blockIdx.x - b*6;
    int t0 = tg * 4;
    const float* g1b = g_g1 + (size_t)b*NN*CT;
    unsigned long long a1p[2][RR], a2p[2][RR];
#pragma unroll
    for (int p = 0; p < 2; p++)
#pragma unroll
        for (int r = 0; r < RR; r++) { a1p[p][r] = 0ull; a2p[p][r] = 0ull; }

    for (int i4 = threadIdx.x * 4; i4 < NCO; i4 += 1024) {
        int n = i4 >> 6, c0 = i4 & 63;
        const float* gp = g1b + (size_t)n*CT + c0*TT + t0;
        unsigned long long gq[4][2];
#pragma unroll
        for (int j = 0; j < 4; j++) {
            ulonglong2 gv = *(const ulonglong2*)(gp + j*TT);
            gq[j][0] = gv.x; gq[j][1] = gv.y;
        }
#pragma unroll
        for (int r = 0; r < RR; r++) {
            float4 f1 = *(const float4*)(g_F1T + (size_t)r*NCO + i4);
            float4 f2 = *(const float4*)(g_F2T + (size_t)r*NCO + i4);
            unsigned long long d;
            d = dup2(f1.x); fma2(a1p[0][r], d, gq[0][0]); fma2(a1p[1][r], d, gq[0][1]);
            d = dup2(f1.y); fma2(a1p[0][r], d, gq[1][0]); fma2(a1p[1][r], d, gq[1][1]);
            d = dup2(f1.z); fma2(a1p[0][r], d, gq[2][0]); fma2(a1p[1][r], d, gq[2][1]);
            d = dup2(f1.w); fma2(a1p[0][r], d, gq[3][0]); fma2(a1p[1][r], d, gq[3][1]);
            d = dup2(f2.x); fma2(a2p[0][r], d, gq[0][0]); fma2(a2p[1][r], d, gq[0][1]);
            d = dup2(f2.y); fma2(a2p[0][r], d, gq[1][0]); fma2(a2p[1][r], d, gq[1][1]);
            d = dup2(f2.z); fma2(a2p[0][r], d, gq[2][0]); fma2(a2p[1][r], d, gq[2][1]);
            d = dup2(f2.w); fma2(a2p[0][r], d, gq[3][0]); fma2(a2p[1][r], d, gq[3][1]);
        }
    }
    __shared__ unsigned long long redu[8][40];
    int lane = threadIdx.x & 31, warp = threadIdx.x >> 5;
#pragma unroll
    for (int p = 0; p < 2; p++)
#pragma unroll
        for (int r = 0; r < RR; r++) {
            unsigned long long v1 = a1p[p][r], v2 = a2p[p][r];
#pragma unroll
            for (int off = 16; off > 0; off >>= 1) {
                float l1 = lo32(v1) + __shfl_down_sync(0xffffffffu, lo32(v1), off);
                float h1 = hi32(v1) + __shfl_down_sync(0xffffffffu, hi32(v1), off);
                float l2 = lo32(v2) + __shfl_down_sync(0xffffffffu, lo32(v2), off);
                float h2 = hi32(v2) + __shfl_down_sync(0xffffffffu, hi32(v2), off);
                v1 = pack2(l1, h1); v2 = pack2(l2, h2);
            }
            if (lane == 0) {
                redu[warp][r*2 + p]      = v1;
                redu[warp][20 + r*2 + p] = v2;
            }
        }
    __syncthreads();
    int tid = threadIdx.x;
    if (tid < 40) {
        float slo = 0.f, shi = 0.f;
#pragma unroll
        for (int w = 0; w < 8; w++) {
            unsigned long long v = redu[w][tid];
            slo += lo32(v); shi += hi32(v);
        }
        int mat = tid / 20;
        int rem = tid - mat*20;
        int r = rem >> 1, p = rem & 1;
        int t = t0 + 2*p;
        if (mat == 0) {
            g_s1t[(b*TT + t)*RR + r]     = slo;
            g_s1t[(b*TT + t + 1)*RR + r] = shi;
        } else {
            g_s2t[(b*RR + r)*TT + t]     = slo;
            g_s2t[(b*RR + r)*TT + t + 1] = shi;
        }
    }
}

// ------------------------- K9: temporal softmax (24x24) --------------------
__global__ void k_tatt_soft() {
    int b = blockIdx.x;
    int i = threadIdx.x;
    if (i >= TT) return;
    float sc[TT];
    float scale = rsqrtf((float)NCO);
#pragma unroll
    for (int j = 0; j < TT; j++) {
        float s = 0.f;
#pragma unroll
        for (int r = 0; r < RR; r++) s += g_s1t[(b*TT + i)*RR + r] * g_s2t[(b*RR + r)*TT + j];
        sc[j] = s * scale;
    }
    float mx = -1e30f;
#pragma unroll
    for (int j = 0; j < TT; j++) mx = fmaxf(mx, sc[j]);
    float sum = 0.f;
#pragma unroll
    for (int j = 0; j < TT; j++) { sc[j] = expf(sc[j] - mx); sum += sc[j]; }
    float inv = 1.f / sum;
#pragma unroll
    for (int j = 0; j < TT; j++) g_attT[(b*TT + i)*TT + j] = sc[j] * inv;
}

// ------------------------- K10: fused mix + tatt-apply + convs + res + LN --
__global__ void __launch_bounds__(256) k_final(
        const float* __restrict__ x,
        const float* __restrict__ gcnW,
        const float* __restrict__ c1b,
        const float* __restrict__ c2b,
        const float* __restrict__ rb,
        const float* __restrict__ lng,
        const float* __restrict__ lnb,
        float* __restrict__ out) {
    __shared__ float smB[4*CT];
    __shared__ float at_s[TT*TT];
    __shared__ float mu_s[4][TT], rs_s[4][TT];
    int blk = blockIdx.x;
    int b = blk / 250;
    int n0 = (blk - b*250) * 4;
    int tid = threadIdx.x;
    int u = tid >> 6, o = tid & 63;
    int n = n0 + u;

    {
        const float* src = g_g1 + ((size_t)b*NN + n0)*CT;
        for (int e4 = tid; e4 < CT; e4 += 256)
            *(float4*)&smB[e4*4] = *(const float4*)(src + e4*4);
    }
    for (int e = tid; e < TT*TT; e += 256) {
        int t = e / TT, tp = e - t*TT;
        at_s[tp*TT + t] = g_attT[b*TT*TT + e];
    }
    __syncthreads();

    unsigned long long gmp[12];
#pragma unroll
    for (int k = 0; k < 12; k++) gmp[k] = 0ull;
#pragma unroll 4
    for (int c = 0; c < CC; c++) {
        unsigned long long wd = dup2(__ldg(gcnW + c*CC + o));
        const unsigned long long* pr = (const unsigned long long*)&smB[u*CT + c*TT];
#pragma unroll
        for (int k = 0; k < 12; k++) fma2(gmp[k], wd, pr[k]);
    }
    float gm[TT];
#pragma unroll
    for (int k = 0; k < 12; k++) { gm[2*k] = lo32(gmp[k]); gm[2*k+1] = hi32(gmp[k]); }

    unsigned long long x2p[12];
#pragma unroll
    for (int k = 0; k < 12; k++) x2p[k] = 0ull;
#pragma unroll 4
    for (int tp = 0; tp < TT; tp++) {
        unsigned long long gd = dup2(gm[tp]);
        const unsigned long long* ar = (const unsigned long long*)&at_s[tp*TT];
#pragma unroll
        for (int k = 0; k < 12; k++) fma2(x2p[k], gd, ar[k]);
    }
    __syncthreads();
    {
        unsigned long long* wp = (unsigned long long*)&smB[u*CT + o*TT];
#pragma unroll
        for (int k = 0; k < 12; k++) wp[k] = x2p[k];
    }
    __syncthreads();

    unsigned long long yp[12];
    {
        unsigned long long bias = dup2(__ldg(c1b + o));
#pragma unroll
        for (int k = 0; k < 12; k++) yp[k] = bias;
#pragma unroll 4
        for (int c = 0; c < CC; c++) {
            const unsigned long long* pr = (const unsigned long long*)&smB[u*CT + c*TT];
            unsigned long long w0d = dup2(__ldg(g_w1T + c*CC + o));
            unsigned long long w1d = dup2(__ldg(g_w1T + CC*CC + c*CC + o));
            unsigned long long tp_[12];
#pragma unroll
            for (int k = 0; k < 12; k++) tp_[k] = pr[k];
#pragma unroll
            for (int k = 0; k < 12; k++) fma2(yp[k], w1d, tp_[k]);
            unsigned long long sh = pack2(0.f, lo32(tp_[0]));
            fma2(yp[0], w0d, sh);
#pragma unroll
            for (int k = 1; k < 12; k++) {
                sh = pack2(hi32(tp_[k-1]), lo32(tp_[k]));
                fma2(yp[k], w0d, sh);
            }
        }
    }
    float y1[TT];
#pragma unroll
    for (int k = 0; k < 12; k++) {
        y1[2*k]   = fmaxf(lo32(yp[k]), 0.f);
        y1[2*k+1] = fmaxf(hi32(yp[k]), 0.f);
    }
    __syncthreads();
    {
        float* wp = &smB[u*CT + o*TT];
#pragma unroll
        for (int k = 0; k < 6; k++)
            *(float4*)(wp + 4*k) = make_float4(y1[4*k], y1[4*k+1], y1[4*k+2], y1[4*k+3]);
    }
    __syncthreads();

    unsigned long long vp[12];
    {
        unsigned long long bias = dup2(__ldg(c2b + o));
#pragma unroll
        for (int k = 0; k < 12; k++) vp[k] = bias;
#pragma unroll 4
        for (int c = 0; c < CC; c++) {
            const unsigned long long* pr = (const unsigned long long*)&smB[u*CT + c*TT];
            unsigned long long w0d = dup2(__ldg(g_w2T + c*CC + o));
            unsigned long long w1d = dup2(__ldg(g_w2T + CC*CC + c*CC + o));
            unsigned long long prev = 0ull;
#pragma unroll
            for (int k = 0; k < 12; k++) {
                unsigned long long cur = pr[k];
                fma2(vp[k], w1d, cur);
                fma2(vp[k], w0d, prev);
                prev = cur;
            }
        }
    }
#pragma unroll
    for (int k = 0; k < 12; k++)
        vp[k] = pack2(fmaxf(lo32(vp[k]), 0.f), fmaxf(hi32(vp[k]), 0.f));
    __syncthreads();

    for (int e4 = tid; e4 < CT; e4 += 256) {
        int f = e4 * 4;
        int u2 = f / CT, rem = f - u2*CT;
        int c = rem / TT, t = rem - c*TT;
        *(float4*)&smB[f] = *(const float4*)(x + (size_t)((b*CC + c)*NN + n0 + u2)*TT + t);
    }
    __syncthreads();

#pragma unroll 4
    for (int c = 0; c < CC; c++) {
        const unsigned long long* pr = (const unsigned long long*)&smB[u*CT + c*TT];
        unsigned long long rwd = dup2(__ldg(g_rT + c*CC + o));
#pragma unroll
        for (int k = 0; k < 12; k++) fma2(vp[k], rwd, pr[k]);
    }
    {
        float biasr = __ldg(rb + o);
#pragma unroll
        for (int k = 0; k < 12; k++) {
            float lo = fmaxf(lo32(vp[k]) + biasr, 0.f);
            float hi = fmaxf(hi32(vp[k]) + biasr, 0.f);
            vp[k] = pack2(lo, hi);
        }
    }
    float v[TT];
#pragma unroll
    for (int k = 0; k < 12; k++) { v[2*k] = lo32(vp[k]); v[2*k+1] = hi32(vp[k]); }
    __syncthreads();

    {
        float* wp = &smB[u*CT + o*TT];
#pragma unroll
        for (int k = 0; k < 6; k++)
            *(float4*)(wp + 4*k) = make_float4(v[4*k], v[4*k+1], v[4*k+2], v[4*k+3]);
    }
    __syncthreads();
    if (tid < 96) {
        int ur = tid / TT, tr = tid - ur*TT;
        float S = 0.f, Q = 0.f;
#pragma unroll 8
        for (int oo = 0; oo < CC; oo++) {
            float val = smB[ur*CT + oo*TT + tr];
            S += val; Q += val*val;
        }
        float mu = S * (1.f/CC);
        float var = Q * (1.f/CC) - mu*mu;
        mu_s[ur][tr] = mu;
        rs_s[ur][tr] = rsqrtf(var + 1e-5f);
    }
    __syncthreads();
    {
        float gmul = __ldg(lng + o), badd = __ldg(lnb + o);
        float* op = out + (size_t)((b*CC + o)*NN + n)*TT;
        float res[TT];
#pragma unroll
        for (int t = 0; t < TT; t++)
            res[t] = (v[t] - mu_s[u][t]) * rs_s[u][t] * gmul + badd;
#pragma unroll
        for (int k = 0; k < 6; k++)
            *(float4*)(op + 4*k) = make_float4(res[4*k], res[4*k+1], res[4*k+2], res[4*k+3]);
    }
}

// ------------------------- launch ------------------------------------------
extern "C" void kernel_launch(void* const* d_in, const int* in_sizes, int n_in,
                              void* d_out, int out_size) {
    const float* x     = (const float*)d_in[0];
    const float* A_adj = (const float*)d_in[1];
    const float* a0W1  = (const float*)d_in[2];
    const float* a0W2  = (const float*)d_in[3];
    const float* gW1   = (const float*)d_in[4];
    const float* gW2   = (const float*)d_in[5];
    const float* gcnW  = (const float*)d_in[6];
    const float* tW1   = (const float*)d_in[7];
    const float* tW2   = (const float*)d_in[8];
    const float* c1w   = (const float*)d_in[9];
    const float* c1b   = (const float*)d_in[10];
    const float* c2w   = (const float*)d_in[11];
    const float* c2b   = (const float*)d_in[12];
    const float* resw  = (const float*)d_in[13];
    const float* resb  = (const float*)d_in[14];
    const float* lng   = (const float*)d_in[15];
    const float* lnb   = (const float*)d_in[16];
    float* out = (float*)d_out;

    k_prep<<<1014, 256>>>(a0W1, gW1, c1w, c2w, resw);
    k_fuse<<<NN, 256>>>(gcnW, tW1, tW2);
    k_attA_proj<<<BB*CC/4, 256>>>(x, a0W2);
    k_attA_soft<<<BB*CC, CC>>>();
    k_chan_apply<<<dim3(NT/64, BB), 256>>>(x);
    k_gatt_proj<<<BB*NN/16, 256>>>(gW2);
    k_gatt_soft<<<BB*NN, 256>>>(A_adj);
    k_gemm<<<dim3(CT/GTN, (NN + GTM - 1)/GTM, BB), 256>>>();
    k_tatt_proj<<<BB*6, 256>>>();
    k_tatt_soft<<<BB, 32>>>();
    k_final<<<BB*NN/4, 256>>>(x, gcnW, c1b, c2b, resb, lng, lnb, out);
}

// round 10
// speedup vs baseline: 1.0807x; 1.0494x over previous
#include <cuda_runtime.h>
#include <math.h>

#define BB 8
#define CC 64
#define NN 1000
#define TT 24
#define RR 10
#define NT 24000     // NN*TT
#define CT 1536      // CC*TT
#define NCO 64000    // NN*CC

// ------------------------- scratch (device globals, no allocs) -------------
__device__ float g_x1t[BB*NN*CT];         // x1 transposed [b][n][(c*T+t)]
__device__ float g_g1[BB*NN*CT];          // Ag @ x1t      [b][n][(c*T+t)]
__device__ float g_s1a[BB*CC*RR];
__device__ float g_s2a[BB*RR*CC];
__device__ float g_att0[BB*CC*CC];
__device__ float g_s1g[BB*NN*RR];
__device__ float g_s2g[BB*RR*NN];
__device__ float g_Ag[BB*NN*NN];          // gated adjacency [b,n,m]
__device__ float g_s1t[BB*TT*RR];
__device__ float g_s2t[BB*RR*TT];
__device__ float g_attT[BB*TT*TT];
// transposed / fused weights
__device__ float g_a0W1T[RR*NT];
__device__ float g_gW1T[RR*CT];
__device__ float g_F1T[RR*NCO];           // fused gcnW . tatt_W1  [r][(n*64+c)]
__device__ float g_F2T[RR*NCO];           // fused gcnW . tatt_W2  [r][(n*64+c)]
__device__ float g_w1T[2*CC*CC];          // conv1 [tap][c][o]
__device__ float g_w2T[2*CC*CC];          // conv2 [tap][c][o]
__device__ float g_rT[CC*CC];             // res_w [c][o]

// ------------------------- f32x2 helpers -----------------------------------
__device__ __forceinline__ unsigned long long dup2(float v) {
    unsigned long long r; unsigned u = __float_as_uint(v);
    asm("mov.b64 %0, {%1, %1};" : "=l"(r) : "r"(u));
    return r;
}
__device__ __forceinline__ unsigned long long pack2(float lo, float hi) {
    unsigned long long r;
    asm("mov.b64 %0, {%1, %2};" : "=l"(r) : "r"(__float_as_uint(lo)), "r"(__float_as_uint(hi)));
    return r;
}
__device__ __forceinline__ void fma2(unsigned long long& d,
                                     unsigned long long a, unsigned long long b) {
    asm("fma.rn.f32x2 %0, %1, %2, %0;" : "+l"(d) : "l"(a), "l"(b));
}
__device__ __forceinline__ float lo32(unsigned long long v) {
    return __uint_as_float((unsigned)v);
}
__device__ __forceinline__ float hi32(unsigned long long v) {
    return __uint_as_float((unsigned)(v >> 32));
}

// ------------------------- K0: weight prep (transposes) --------------------
__global__ void k_prep(const float* __restrict__ a0W1, const float* __restrict__ gW1,
                       const float* __restrict__ c1w, const float* __restrict__ c2w,
                       const float* __restrict__ rw) {
    int e = blockIdx.x * 256 + threadIdx.x;
    if (e < NT*RR)  { int k = e/RR, r = e - k*RR; g_a0W1T[r*NT + k] = a0W1[e]; return; }
    e -= NT*RR;
    if (e < CT*RR)  { int k = e/RR, r = e - k*RR; g_gW1T[r*CT + k] = gW1[e]; return; }
    e -= CT*RR;
    if (e < CC*CC) {
        int o = e >> 6, c = e & 63;
        g_w1T[c*CC + o]         = c1w[e*2 + 0];
        g_w1T[CC*CC + c*CC + o] = c1w[e*2 + 1];
        g_w2T[c*CC + o]         = c2w[e*2 + 0];
        g_w2T[CC*CC + c*CC + o] = c2w[e*2 + 1];
        g_rT[c*CC + o]          = rw[e];
    }
}

// ------------------------- K0b: fuse gcn_W into tatt weights ---------------
__global__ void k_fuse(const float* __restrict__ gcnW, const float* __restrict__ tW1,
                       const float* __restrict__ tW2) {
    int n = blockIdx.x;
    __shared__ float gs[CC*CC];
    __shared__ float w1s[CC*RR];
    __shared__ float w2s[RR*CC];
    int tid = threadIdx.x;
    for (int e = tid; e < CC*CC; e += 256) gs[e] = gcnW[e];
    for (int e = tid; e < CC*RR; e += 256) w1s[e] = tW1[(size_t)(n*CC)*RR + e];
    for (int e = tid; e < RR*CC; e += 256) {
        int r = e / CC, o = e - r*CC;
        w2s[e] = tW2[(size_t)r*NCO + n*CC + o];
    }
    __syncthreads();
    for (int idx = tid; idx < CC*RR; idx += 256) {
        int c = idx / RR, r = idx - c*RR;
        float s1 = 0.f, s2 = 0.f;
#pragma unroll 16
        for (int o = 0; o < CC; o++) {
            float g = gs[c*CC + o];
            s1 += g * w1s[o*RR + r];
            s2 += g * w2s[r*CC + o];
        }
        g_F1T[(size_t)r*NCO + n*CC + c] = s1;
        g_F2T[(size_t)r*NCO + n*CC + c] = s2;
    }
}

// ------------------------- K1: channel-attn projections (4 rows/block) -----
__global__ void __launch_bounds__(256) k_attA_proj(const float* __restrict__ x,
                                                   const float* __restrict__ W2) {
    int g0 = blockIdx.x * 4;
    float a1[4][RR], a2[4][RR];
#pragma unroll
    for (int j = 0; j < 4; j++)
#pragma unroll
        for (int r = 0; r < RR; r++) { a1[j][r] = 0.f; a2[j][r] = 0.f; }
    for (int k4 = threadIdx.x * 4; k4 < NT; k4 += 1024) {
        float4 xv[4];
#pragma unroll
        for (int j = 0; j < 4; j++)
            xv[j] = *(const float4*)(x + (size_t)(g0 + j)*NT + k4);
#pragma unroll
        for (int r = 0; r < RR; r++) {
            float4 w1 = *(const float4*)(g_a0W1T + r*NT + k4);
            float4 w2 = *(const float4*)(W2 + r*NT + k4);
#pragma unroll
            for (int j = 0; j < 4; j++) {
                a1[j][r] += xv[j].x*w1.x + xv[j].y*w1.y + xv[j].z*w1.z + xv[j].w*w1.w;
                a2[j][r] += xv[j].x*w2.x + xv[j].y*w2.y + xv[j].z*w2.z + xv[j].w*w2.w;
            }
        }
    }
    __shared__ float red[8][80];
    int lane = threadIdx.x & 31, warp = threadIdx.x >> 5;
#pragma unroll
    for (int j = 0; j < 4; j++)
#pragma unroll
        for (int r = 0; r < RR; r++) {
#pragma unroll
            for (int off = 16; off > 0; off >>= 1) {
                a1[j][r] += __shfl_down_sync(0xffffffffu, a1[j][r], off);
                a2[j][r] += __shfl_down_sync(0xffffffffu, a2[j][r], off);
            }
            if (lane == 0) { red[warp][j*RR + r] = a1[j][r]; red[warp][40 + j*RR + r] = a2[j][r]; }
        }
    __syncthreads();
    int tid = threadIdx.x;
    if (tid < 80) {
        float s = 0.f;
#pragma unroll
        for (int w = 0; w < 8; w++) s += red[w][tid];
        if (tid < 40) {
            int j = tid / RR, r = tid - j*RR;
            g_s1a[(g0 + j)*RR + r] = s;
        } else {
            int k = tid - 40;
            int j = k / RR, r = k - j*RR;
            int bc = g0 + j, b = bc >> 6, c = bc & 63;
            g_s2a[(b*RR + r)*CC + c] = s;
        }
    }
}

// ------------------------- K2: channel-attn softmax (64x64) ----------------
__global__ void k_attA_soft() {
    int b = blockIdx.x >> 6, i = blockIdx.x & 63;
    int j = threadIdx.x;
    float s = 0.f;
#pragma unroll
    for (int r = 0; r < RR; r++) s += g_s1a[(b*CC + i)*RR + r] * g_s2a[(b*RR + r)*CC + j];
    s *= rsqrtf((float)NT);
    __shared__ float sm[CC];
    sm[j] = s; __syncthreads();
    float mx = -1e30f;
    for (int jj = 0; jj < CC; jj++) mx = fmaxf(mx, sm[jj]);
    float e = expf(s - mx);
    __syncthreads();
    sm[j] = e; __syncthreads();
    float sum = 0.f;
    for (int jj = 0; jj < CC; jj++) sum += sm[jj];
    g_att0[(b*CC + i)*CC + j] = e / sum;
}

// ------------------------- K3: x1t = att0 @ xf (transposed out, vec4) ------
__global__ void __launch_bounds__(256) k_chan_apply(const float* __restrict__ x) {
    int b = blockIdx.y;
    int k0 = blockIdx.x * 64;
    __shared__ float atts[CC][68];
    __shared__ float xfs[CC][64];
    int tid = threadIdx.x;
    for (int e = tid; e < CC*CC; e += 256) {
        int c = e >> 6, j = e & 63;
        atts[j][c] = g_att0[b*CC*CC + e];
    }
    for (int e = tid; e < CC*64; e += 256) {
        int j = e >> 6, kk = e & 63;
        xfs[j][kk] = x[(size_t)(b*CC + j)*NT + k0 + kk];
    }
    __syncthreads();
    int tx = tid & 15, ty = tid >> 4;
    unsigned long long acc[4][2];
#pragma unroll
    for (int i = 0; i < 4; i++) { acc[i][0] = 0ull; acc[i][1] = 0ull; }
#pragma unroll 4
    for (int j = 0; j < CC; j++) {
        float4 a = *(const float4*)&atts[j][ty*4];
        ulonglong2 xv = *(const ulonglong2*)&xfs[j][tx*4];
        unsigned long long d0 = dup2(a.x), d1 = dup2(a.y), d2 = dup2(a.z), d3 = dup2(a.w);
        fma2(acc[0][0], d0, xv.x); fma2(acc[0][1], d0, xv.y);
        fma2(acc[1][0], d1, xv.x); fma2(acc[1][1], d1, xv.y);
        fma2(acc[2][0], d2, xv.x); fma2(acc[2][1], d2, xv.y);
        fma2(acc[3][0], d3, xv.x); fma2(acc[3][1], d3, xv.y);
    }
    // 4 consecutive kk share one n row and t0 % 4 == 0 -> float4 stores
    int kk0 = k0 + tx*4;
    int n = kk0 / TT, t0 = kk0 - n*TT;
    float* basep = &g_x1t[((size_t)b*NN + n)*CT + t0];
#pragma unroll
    for (int ci = 0; ci < 4; ci++) {
        int c = ty*4 + ci;
        *(float4*)(basep + c*TT) =
            make_float4(lo32(acc[ci][0]), hi32(acc[ci][0]),
                        lo32(acc[ci][1]), hi32(acc[ci][1]));
    }
}

// ------------------------- K4: graph-attn projections (16 rows/block) ------
__global__ void __launch_bounds__(256) k_gatt_proj(const float* __restrict__ W2) {
    int base = blockIdx.x * 16;
    __shared__ float red[8][2*RR];
    int lane = threadIdx.x & 31, warp = threadIdx.x >> 5;
    for (int row = 0; row < 16; row++) {
        int bn = base + row;
        int b = bn / NN, n = bn - b*NN;
        const float* xf = g_x1t + (size_t)bn * CT;
        float a1[RR], a2[RR];
#pragma unroll
        for (int r = 0; r < RR; r++) { a1[r] = 0.f; a2[r] = 0.f; }
        for (int k4 = threadIdx.x * 4; k4 < CT; k4 += 1024) {
            float4 xv = *(const float4*)(xf + k4);
#pragma unroll
            for (int r = 0; r < RR; r++) {
                float4 w1 = *(const float4*)(g_gW1T + r*CT + k4);
                float4 w2 = *(const float4*)(W2 + r*CT + k4);
                a1[r] += xv.x*w1.x + xv.y*w1.y + xv.z*w1.z + xv.w*w1.w;
                a2[r] += xv.x*w2.x + xv.y*w2.y + xv.z*w2.z + xv.w*w2.w;
            }
        }
#pragma unroll
        for (int r = 0; r < RR; r++) {
#pragma unroll
            for (int off = 16; off > 0; off >>= 1) {
                a1[r] += __shfl_down_sync(0xffffffffu, a1[r], off);
                a2[r] += __shfl_down_sync(0xffffffffu, a2[r], off);
            }
        }
        if (lane == 0) {
#pragma unroll
            for (int r = 0; r < RR; r++) { red[warp][r] = a1[r]; red[warp][RR+r] = a2[r]; }
        }
        __syncthreads();
        if (threadIdx.x < 2*RR) {
            float s = 0.f;
#pragma unroll
            for (int w = 0; w < 8; w++) s += red[w][threadIdx.x];
            if (threadIdx.x < RR) g_s1g[(size_t)bn*RR + threadIdx.x] = s;
            else                  g_s2g[((size_t)b*RR + (threadIdx.x - RR))*NN + n] = s;
        }
        __syncthreads();
    }
}

// ------------------------- K5: graph softmax * A_adj (no-max, 1 pass) ------
__global__ void k_gatt_soft(const float* __restrict__ A_adj) {
    int bi = blockIdx.x;
    int b = bi / NN, i = bi - b*NN;
    __shared__ float sc[NN];
    __shared__ float s1r[RR];
    __shared__ float red[256];
    int tid = threadIdx.x;
    if (tid < RR) s1r[tid] = g_s1g[(size_t)(b*NN + i)*RR + tid];
    __syncthreads();
    float scale = rsqrtf((float)CT);
    float lsum = 0.f;
    for (int j = tid; j < NN; j += 256) {
        float s = 0.f;
#pragma unroll
        for (int r = 0; r < RR; r++) s += s1r[r] * g_s2g[(size_t)(b*RR + r)*NN + j];
        float e = expf(s * scale);          // scores ~1e-3: max-subtract unnecessary
        sc[j] = e;
        lsum += e;
    }
    red[tid] = lsum; __syncthreads();
    for (int off = 128; off > 0; off >>= 1) {
        if (tid < off) red[tid] += red[tid + off];
        __syncthreads();
    }
    float inv = 1.f / red[0];
    for (int j = tid; j < NN; j += 256) {
        g_Ag[((size_t)b*NN + i)*NN + j] = sc[j] * inv * A_adj[i*NN + j];
    }
}

// ------------------------- K7: big GEMM g1 = Ag @ x1t (f32x2) --------------
#define GTM 128
#define GTN 128
#define GTK 16
__global__ void __launch_bounds__(256, 2) k_gemm() {
    int b  = blockIdx.z;
    int n0 = blockIdx.y * GTM;
    int j0 = blockIdx.x * GTN;
    const float* A  = g_Ag  + (size_t)b*NN*NN;
    const float* Bm = g_x1t + (size_t)b*NN*CT;
    float*       Cm = g_g1  + (size_t)b*NN*CT;
    __shared__ float As[2][GTK][GTM + 4];
    __shared__ float Bs[2][GTK][GTN + 4];
    int tid = threadIdx.x;
    int tx = tid & 15;
    int ty = tid >> 4;
    int an = tid >> 1, ah = (tid & 1) * 8;
    int bk = tid >> 4, bj = (tid & 15) * 8;
    const float4 z4 = make_float4(0.f, 0.f, 0.f, 0.f);

    unsigned long long acc[8][4];
#pragma unroll
    for (int i = 0; i < 8; i++)
#pragma unroll
        for (int j = 0; j < 4; j++) acc[i][j] = 0ull;

    const int NKT = (NN + GTK - 1) / GTK;      // 63
    {
        int n = n0 + an;
        bool va = (n < NN) && (ah < NN);
        const float* pA = A + (size_t)n*NN + ah;
        float4 a0 = va ? *(const float4*)pA : z4;
        float4 a1 = va ? *(const float4*)(pA + 4) : z4;
        As[0][ah + 0][an] = a0.x; As[0][ah + 1][an] = a0.y;
        As[0][ah + 2][an] = a0.z; As[0][ah + 3][an] = a0.w;
        As[0][ah + 4][an] = a1.x; As[0][ah + 5][an] = a1.y;
        As[0][ah + 6][an] = a1.z; As[0][ah + 7][an] = a1.w;
        const float* pB = Bm + (size_t)bk*CT + j0 + bj;
        *(float4*)&Bs[0][bk][bj]     = *(const float4*)pB;
        *(float4*)&Bs[0][bk][bj + 4] = *(const float4*)(pB + 4);
    }
    __syncthreads();

    for (int kt = 0; kt < NKT; kt++) {
        int buf = kt & 1;
        float4 pa0, pa1, pb0, pb1;
        bool have_next = (kt + 1 < NKT);
        if (have_next) {
            int k0 = (kt + 1) * GTK;
            int n = n0 + an;
            bool va = (n < NN) && (k0 + ah < NN);
            const float* pA = A + (size_t)n*NN + k0 + ah;
            pa0 = va ? *(const float4*)pA : z4;
            pa1 = va ? *(const float4*)(pA + 4) : z4;
            bool vb = (k0 + bk < NN);
            const float* pB = Bm + (size_t)(k0 + bk)*CT + j0 + bj;
            pb0 = vb ? *(const float4*)pB : z4;
            pb1 = vb ? *(const float4*)(pB + 4) : z4;
        }
#pragma unroll
        for (int kk = 0; kk < GTK; kk++) {
            float4 a0 = *(const float4*)&As[buf][kk][ty*8];
            float4 a1 = *(const float4*)&As[buf][kk][ty*8 + 4];
            ulonglong2 b0 = *(const ulonglong2*)&Bs[buf][kk][tx*8];
            ulonglong2 b1 = *(const ulonglong2*)&Bs[buf][kk][tx*8 + 4];
            unsigned long long ad[8];
            ad[0] = dup2(a0.x); ad[1] = dup2(a0.y); ad[2] = dup2(a0.z); ad[3] = dup2(a0.w);
            ad[4] = dup2(a1.x); ad[5] = dup2(a1.y); ad[6] = dup2(a1.z); ad[7] = dup2(a1.w);
#pragma unroll
            for (int i = 0; i < 8; i++) {
                fma2(acc[i][0], ad[i], b0.x);
                fma2(acc[i][1], ad[i], b0.y);
                fma2(acc[i][2], ad[i], b1.x);
                fma2(acc[i][3], ad[i], b1.y);
            }
        }
        if (have_next) {
            int nb = buf ^ 1;
            As[nb][ah + 0][an] = pa0.x; As[nb][ah + 1][an] = pa0.y;
            As[nb][ah + 2][an] = pa0.z; As[nb][ah + 3][an] = pa0.w;
            As[nb][ah + 4][an] = pa1.x; As[nb][ah + 5][an] = pa1.y;
            As[nb][ah + 6][an] = pa1.z; As[nb][ah + 7][an] = pa1.w;
            *(float4*)&Bs[nb][bk][bj]     = pb0;
            *(float4*)&Bs[nb][bk][bj + 4] = pb1;
        }
        __syncthreads();
    }
#pragma unroll
    for (int i = 0; i < 8; i++) {
        int n = n0 + ty*8 + i;
        if (n < NN) {
            float* cp = Cm + (size_t)n*CT + j0 + tx*8;
            float4 v0 = make_float4(lo32(acc[i][0]), hi32(acc[i][0]),
                                    lo32(acc[i][1]), hi32(acc[i][1]));
            float4 v1 = make_float4(lo32(acc[i][2]), hi32(acc[i][2]),
                                    lo32(acc[i][3]), hi32(acc[i][3]));
            *(float4*)cp = v0;
            *(float4*)(cp + 4) = v1;
        }
    }
}

// ------------------------- K8: temporal-attn projections (r-split, 96 blk) -
__global__ void __launch_bounds__(256) k_tatt_proj() {
    int z  = blockIdx.x;
    int rh = z & 1;                            // r-half: rows rh*5 .. rh*5+4
    int bt = z >> 1;
    int b  = bt / 6;
    int tg = bt - b*6;
    int t0 = tg * 4;
    const float* g1b = g_g1 + (size_t)b*NN*CT;
    unsigned long long a1p[2][5], a2p[2][5];
#pragma unroll
    for (int p = 0; p < 2; p++)
#pragma unroll
        for (int r = 0; r < 5; r++) { a1p[p][r] = 0ull; a2p[p][r] = 0ull; }

    for (int i4 = threadIdx.x * 4; i4 < NCO; i4 += 1024) {
        int n = i4 >> 6, c0 = i4 & 63;
        const float* gp = g1b + (size_t)n*CT + c0*TT + t0;
        unsigned long long gq[4][2];
#pragma unroll
        for (int j = 0; j < 4; j++) {
            ulonglong2 gv = *(const ulonglong2*)(gp + j*TT);
            gq[j][0] = gv.x; gq[j][1] = gv.y;
        }
#pragma unroll
        for (int r = 0; r < 5; r++) {
            int rr = rh*5 + r;
            float4 f1 = *(const float4*)(g_F1T + (size_t)rr*NCO + i4);
            float4 f2 = *(const float4*)(g_F2T + (size_t)rr*NCO + i4);
            unsigned long long d;
            d = dup2(f1.x); fma2(a1p[0][r], d, gq[0][0]); fma2(a1p[1][r], d, gq[0][1]);
            d = dup2(f1.y); fma2(a1p[0][r], d, gq[1][0]); fma2(a1p[1][r], d, gq[1][1]);
            d = dup2(f1.z); fma2(a1p[0][r], d, gq[2][0]); fma2(a1p[1][r], d, gq[2][1]);
            d = dup2(f1.w); fma2(a1p[0][r], d, gq[3][0]); fma2(a1p[1][r], d, gq[3][1]);
            d = dup2(f2.x); fma2(a2p[0][r], d, gq[0][0]); fma2(a2p[1][r], d, gq[0][1]);
            d = dup2(f2.y); fma2(a2p[0][r], d, gq[1][0]); fma2(a2p[1][r], d, gq[1][1]);
            d = dup2(f2.z); fma2(a2p[0][r], d, gq[2][0]); fma2(a2p[1][r], d, gq[2][1]);
            d = dup2(f2.w); fma2(a2p[0][r], d, gq[3][0]); fma2(a2p[1][r], d, gq[3][1]);
        }
    }
    __shared__ unsigned long long redu[8][20];
    int lane = threadIdx.x & 31, warp = threadIdx.x >> 5;
#pragma unroll
    for (int p = 0; p < 2; p++)
#pragma unroll
        for (int r = 0; r < 5; r++) {
            unsigned long long v1 = a1p[p][r], v2 = a2p[p][r];
#pragma unroll
            for (int off = 16; off > 0; off >>= 1) {
                float l1 = lo32(v1) + __shfl_down_sync(0xffffffffu, lo32(v1), off);
                float h1 = hi32(v1) + __shfl_down_sync(0xffffffffu, hi32(v1), off);
                float l2 = lo32(v2) + __shfl_down_sync(0xffffffffu, lo32(v2), off);
                float h2 = hi32(v2) + __shfl_down_sync(0xffffffffu, hi32(v2), off);
                v1 = pack2(l1, h1); v2 = pack2(l2, h2);
            }
            if (lane == 0) {
                redu[warp][r*2 + p]      = v1;
                redu[warp][10 + r*2 + p] = v2;
            }
        }
    __syncthreads();
    int tid = threadIdx.x;
    if (tid < 20) {
        float slo = 0.f, shi = 0.f;
#pragma unroll
        for (int w = 0; w < 8; w++) {
            unsigned long long v = redu[w][tid];
            slo += lo32(v); shi += hi32(v);
        }
        int mat = tid / 10;
        int rem = tid - mat*10;
        int r = rem >> 1, p = rem & 1;
        int rr = rh*5 + r;
        int t = t0 + 2*p;
        if (mat == 0) {
            g_s1t[(b*TT + t)*RR + rr]     = slo;
            g_s1t[(b*TT + t + 1)*RR + rr] = shi;
        } else {
            g_s2t[(b*RR + rr)*TT + t]     = slo;
            g_s2t[(b*RR + rr)*TT + t + 1] = shi;
        }
    }
}

// ------------------------- K9: temporal softmax (24x24) --------------------
__global__ void k_tatt_soft() {
    int b = blockIdx.x;
    int i = threadIdx.x;
    if (i >= TT) return;
    float sc[TT];
    float scale = rsqrtf((float)NCO);
#pragma unroll
    for (int j = 0; j < TT; j++) {
        float s = 0.f;
#pragma unroll
        for (int r = 0; r < RR; r++) s += g_s1t[(b*TT + i)*RR + r] * g_s2t[(b*RR + r)*TT + j];
        sc[j] = s * scale;
    }
    float mx = -1e30f;
#pragma unroll
    for (int j = 0; j < TT; j++) mx = fmaxf(mx, sc[j]);
    float sum = 0.f;
#pragma unroll
    for (int j = 0; j < TT; j++) { sc[j] = expf(sc[j] - mx); sum += sc[j]; }
    float inv = 1.f / sum;
#pragma unroll
    for (int j = 0; j < TT; j++) g_attT[(b*TT + i)*TT + j] = sc[j] * inv;
}

// ------------------------- K10: fused mix + tatt-apply + convs + res + LN --
__global__ void __launch_bounds__(256) k_final(
        const float* __restrict__ x,
        const float* __restrict__ gcnW,
        const float* __restrict__ c1b,
        const float* __restrict__ c2b,
        const float* __restrict__ rb,
        const float* __restrict__ lng,
        const float* __restrict__ lnb,
        float* __restrict__ out) {
    __shared__ float smB[4*CT];
    __shared__ float at_s[TT*TT];
    __shared__ float mu_s[4][TT], rs_s[4][TT];
    int blk = blockIdx.x;
    int b = blk / 250;
    int n0 = (blk - b*250) * 4;
    int tid = threadIdx.x;
    int u = tid >> 6, o = tid & 63;
    int n = n0 + u;

    {
        const float* src = g_g1 + ((size_t)b*NN + n0)*CT;
        for (int e4 = tid; e4 < CT; e4 += 256)
            *(float4*)&smB[e4*4] = *(const float4*)(src + e4*4);
    }
    for (int e = tid; e < TT*TT; e += 256) {
        int t = e / TT, tp = e - t*TT;
        at_s[tp*TT + t] = g_attT[b*TT*TT + e];
    }
    __syncthreads();

    unsigned long long gmp[12];
#pragma unroll
    for (int k = 0; k < 12; k++) gmp[k] = 0ull;
#pragma unroll 4
    for (int c = 0; c < CC; c++) {
        unsigned long long wd = dup2(__ldg(gcnW + c*CC + o));
        const unsigned long long* pr = (const unsigned long long*)&smB[u*CT + c*TT];
#pragma unroll
        for (int k = 0; k < 12; k++) fma2(gmp[k], wd, pr[k]);
    }
    float gm[TT];
#pragma unroll
    for (int k = 0; k < 12; k++) { gm[2*k] = lo32(gmp[k]); gm[2*k+1] = hi32(gmp[k]); }

    unsigned long long x2p[12];
#pragma unroll
    for (int k = 0; k < 12; k++) x2p[k] = 0ull;
#pragma unroll 4
    for (int tp = 0; tp < TT; tp++) {
        unsigned long long gd = dup2(gm[tp]);
        const unsigned long long* ar = (const unsigned long long*)&at_s[tp*TT];
#pragma unroll
        for (int k = 0; k < 12; k++) fma2(x2p[k], gd, ar[k]);
    }
    __syncthreads();
    {
        unsigned long long* wp = (unsigned long long*)&smB[u*CT + o*TT];
#pragma unroll
        for (int k = 0; k < 12; k++) wp[k] = x2p[k];
    }
    __syncthreads();

    unsigned long long yp[12];
    {
        unsigned long long bias = dup2(__ldg(c1b + o));
#pragma unroll
        for (int k = 0; k < 12; k++) yp[k] = bias;
#pragma unroll 4
        for (int c = 0; c < CC; c++) {
            const unsigned long long* pr = (const unsigned long long*)&smB[u*CT + c*TT];
            unsigned long long w0d = dup2(__ldg(g_w1T + c*CC + o));
            unsigned long long w1d = dup2(__ldg(g_w1T + CC*CC + c*CC + o));
            unsigned long long tp_[12];
#pragma unroll
            for (int k = 0; k < 12; k++) tp_[k] = pr[k];
#pragma unroll
            for (int k = 0; k < 12; k++) fma2(yp[k], w1d, tp_[k]);
            unsigned long long sh = pack2(0.f, lo32(tp_[0]));
            fma2(yp[0], w0d, sh);
#pragma unroll
            for (int k = 1; k < 12; k++) {
                sh = pack2(hi32(tp_[k-1]), lo32(tp_[k]));
                fma2(yp[k], w0d, sh);
            }
        }
    }
    float y1[TT];
#pragma unroll
    for (int k = 0; k < 12; k++) {
        y1[2*k]   = fmaxf(lo32(yp[k]), 0.f);
        y1[2*k+1] = fmaxf(hi32(yp[k]), 0.f);
    }
    __syncthreads();
    {
        float* wp = &smB[u*CT + o*TT];
#pragma unroll
        for (int k = 0; k < 6; k++)
            *(float4*)(wp + 4*k) = make_float4(y1[4*k], y1[4*k+1], y1[4*k+2], y1[4*k+3]);
    }
    __syncthreads();

    unsigned long long vp[12];
    {
        unsigned long long bias = dup2(__ldg(c2b + o));
#pragma unroll
        for (int k = 0; k < 12; k++) vp[k] = bias;
#pragma unroll 4
        for (int c = 0; c < CC; c++) {
            const unsigned long long* pr = (const unsigned long long*)&smB[u*CT + c*TT];
            unsigned long long w0d = dup2(__ldg(g_w2T + c*CC + o));
            unsigned long long w1d = dup2(__ldg(g_w2T + CC*CC + c*CC + o));
            unsigned long long prev = 0ull;
#pragma unroll
            for (int k = 0; k < 12; k++) {
                unsigned long long cur = pr[k];
                fma2(vp[k], w1d, cur);
                fma2(vp[k], w0d, prev);
                prev = cur;
            }
        }
    }
#pragma unroll
    for (int k = 0; k < 12; k++)
        vp[k] = pack2(fmaxf(lo32(vp[k]), 0.f), fmaxf(hi32(vp[k]), 0.f));
    __syncthreads();

    for (int e4 = tid; e4 < CT; e4 += 256) {
        int f = e4 * 4;
        int u2 = f / CT, rem = f - u2*CT;
        int c = rem / TT, t = rem - c*TT;
        *(float4*)&smB[f] = *(const float4*)(x + (size_t)((b*CC + c)*NN + n0 + u2)*TT + t);
    }
    __syncthreads();

#pragma unroll 4
    for (int c = 0; c < CC; c++) {
        const unsigned long long* pr = (const unsigned long long*)&smB[u*CT + c*TT];
        unsigned long long rwd = dup2(__ldg(g_rT + c*CC + o));
#pragma unroll
        for (int k = 0; k < 12; k++) fma2(vp[k], rwd, pr[k]);
    }
    {
        float biasr = __ldg(rb + o);
#pragma unroll
        for (int k = 0; k < 12; k++) {
            float lo = fmaxf(lo32(vp[k]) + biasr, 0.f);
            float hi = fmaxf(hi32(vp[k]) + biasr, 0.f);
            vp[k] = pack2(lo, hi);
        }
    }
    float v[TT];
#pragma unroll
    for (int k = 0; k < 12; k++) { v[2*k] = lo32(vp[k]); v[2*k+1] = hi32(vp[k]); }
    __syncthreads();

    {
        float* wp = &smB[u*CT + o*TT];
#pragma unroll
        for (int k = 0; k < 6; k++)
            *(float4*)(wp + 4*k) = make_float4(v[4*k], v[4*k+1], v[4*k+2], v[4*k+3]);
    }
    __syncthreads();
    if (tid < 96) {
        int ur = tid / TT, tr = tid - ur*TT;
        float S = 0.f, Q = 0.f;
#pragma unroll 8
        for (int oo = 0; oo < CC; oo++) {
            float val = smB[ur*CT + oo*TT + tr];
            S += val; Q += val*val;
        }
        float mu = S * (1.f/CC);
        float var = Q * (1.f/CC) - mu*mu;
        mu_s[ur][tr] = mu;
        rs_s[ur][tr] = rsqrtf(var + 1e-5f);
    }
    __syncthreads();
    {
        float gmul = __ldg(lng + o), badd = __ldg(lnb + o);
        float* op = out + (size_t)((b*CC + o)*NN + n)*TT;
        float res[TT];
#pragma unroll
        for (int t = 0; t < TT; t++)
            res[t] = (v[t] - mu_s[u][t]) * rs_s[u][t] * gmul + badd;
#pragma unroll
        for (int k = 0; k < 6; k++)
            *(float4*)(op + 4*k) = make_float4(res[4*k], res[4*k+1], res[4*k+2], res[4*k+3]);
    }
}

// ------------------------- launch ------------------------------------------
extern "C" void kernel_launch(void* const* d_in, const int* in_sizes, int n_in,
                              void* d_out, int out_size) {
    const float* x     = (const float*)d_in[0];
    const float* A_adj = (const float*)d_in[1];
    const float* a0W1  = (const float*)d_in[2];
    const float* a0W2  = (const float*)d_in[3];
    const float* gW1   = (const float*)d_in[4];
    const float* gW2   = (const float*)d_in[5];
    const float* gcnW  = (const float*)d_in[6];
    const float* tW1   = (const float*)d_in[7];
    const float* tW2   = (const float*)d_in[8];
    const float* c1w   = (const float*)d_in[9];
    const float* c1b   = (const float*)d_in[10];
    const float* c2w   = (const float*)d_in[11];
    const float* c2b   = (const float*)d_in[12];
    const float* resw  = (const float*)d_in[13];
    const float* resb  = (const float*)d_in[14];
    const float* lng   = (const float*)d_in[15];
    const float* lnb   = (const float*)d_in[16];
    float* out = (float*)d_out;

    k_prep<<<1014, 256>>>(a0W1, gW1, c1w, c2w, resw);
    k_fuse<<<NN, 256>>>(gcnW, tW1, tW2);
    k_attA_proj<<<BB*CC/4, 256>>>(x, a0W2);
    k_attA_soft<<<BB*CC, CC>>>();
    k_chan_apply<<<dim3(NT/64, BB), 256>>>(x);
    k_gatt_proj<<<BB*NN/16, 256>>>(gW2);
    k_gatt_soft<<<BB*NN, 256>>>(A_adj);
    k_gemm<<<dim3(CT/GTN, (NN + GTM - 1)/GTM, BB), 256>>>();
    k_tatt_proj<<<BB*6*2, 256>>>();
    k_tatt_soft<<<BB, 32>>>();
    k_final<<<BB*NN/4, 256>>>(x, gcnW, c1b, c2b, resb, lng, lnb, out);
}

// round 12
// speedup vs baseline: 1.2111x; 1.1207x over previous
#include <cuda_runtime.h>
#include <cuda_fp16.h>
#include <math.h>

#define BB 8
#define CC 64
#define NN 1000
#define TT 24
#define RR 10
#define NT 24000     // NN*TT
#define CT 1536      // CC*TT
#define NCO 64000    // NN*CC

// ------------------------- scratch (device globals, no allocs) -------------
__device__ float  g_x1t[BB*NN*CT];        // x1 transposed [b][n][(c*T+t)] fp32
__device__ __half g_x1h[BB*NN*CT];        // fp16 copy for GEMM B
__device__ __half g_Agh[BB*NN*NN];        // gated adjacency fp16 [b][n][m]
__device__ float  g_g1[BB*NN*CT];         // Ag @ x1t  [b][n][(c*T+t)]
__device__ float g_s1a[BB*CC*RR];
__device__ float g_s2a[BB*RR*CC];
__device__ float g_att0[BB*CC*CC];
__device__ float g_s1g[BB*NN*RR];
__device__ float g_s2g[BB*RR*NN];
__device__ float g_s1t[BB*TT*RR];
__device__ float g_s2t[BB*RR*TT];
__device__ float g_attT[BB*TT*TT];
// transposed / fused weights
__device__ float g_a0W1T[RR*NT];
__device__ float g_gW1T[RR*CT];
__device__ float g_F1T[RR*NCO];
__device__ float g_F2T[RR*NCO];
__device__ float g_w1T[2*CC*CC];
__device__ float g_w2T[2*CC*CC];
__device__ float g_rT[CC*CC];

// ------------------------- f32x2 helpers -----------------------------------
__device__ __forceinline__ unsigned long long dup2(float v) {
    unsigned long long r; unsigned u = __float_as_uint(v);
    asm("mov.b64 %0, {%1, %1};" : "=l"(r) : "r"(u));
    return r;
}
__device__ __forceinline__ unsigned long long pack2(float lo, float hi) {
    unsigned long long r;
    asm("mov.b64 %0, {%1, %2};" : "=l"(r) : "r"(__float_as_uint(lo)), "r"(__float_as_uint(hi)));
    return r;
}
__device__ __forceinline__ void fma2(unsigned long long& d,
                                     unsigned long long a, unsigned long long b) {
    asm("fma.rn.f32x2 %0, %1, %2, %0;" : "+l"(d) : "l"(a), "l"(b));
}
__device__ __forceinline__ float lo32(unsigned long long v) {
    return __uint_as_float((unsigned)v);
}
__device__ __forceinline__ float hi32(unsigned long long v) {
    return __uint_as_float((unsigned)(v >> 32));
}

// ------------------------- K0: weight prep (transposes) --------------------
__global__ void k_prep(const float* __restrict__ a0W1, const float* __restrict__ gW1,
                       const float* __restrict__ c1w, const float* __restrict__ c2w,
                       const float* __restrict__ rw) {
    int e = blockIdx.x * 256 + threadIdx.x;
    if (e < NT*RR)  { int k = e/RR, r = e - k*RR; g_a0W1T[r*NT + k] = a0W1[e]; return; }
    e -= NT*RR;
    if (e < CT*RR)  { int k = e/RR, r = e - k*RR; g_gW1T[r*CT + k] = gW1[e]; return; }
    e -= CT*RR;
    if (e < CC*CC) {
        int o = e >> 6, c = e & 63;
        g_w1T[c*CC + o]         = c1w[e*2 + 0];
        g_w1T[CC*CC + c*CC + o] = c1w[e*2 + 1];
        g_w2T[c*CC + o]         = c2w[e*2 + 0];
        g_w2T[CC*CC + c*CC + o] = c2w[e*2 + 1];
        g_rT[c*CC + o]          = rw[e];
    }
}

// ------------------------- K0b: fuse gcn_W into tatt weights ---------------
__global__ void k_fuse(const float* __restrict__ gcnW, const float* __restrict__ tW1,
                       const float* __restrict__ tW2) {
    int n = blockIdx.x;
    __shared__ float gs[CC*CC];
    __shared__ float w1s[CC*RR];
    __shared__ float w2s[RR*CC];
    int tid = threadIdx.x;
    for (int e = tid; e < CC*CC; e += 256) gs[e] = gcnW[e];
    for (int e = tid; e < CC*RR; e += 256) w1s[e] = tW1[(size_t)(n*CC)*RR + e];
    for (int e = tid; e < RR*CC; e += 256) {
        int r = e / CC, o = e - r*CC;
        w2s[e] = tW2[(size_t)r*NCO + n*CC + o];
    }
    __syncthreads();
    for (int idx = tid; idx < CC*RR; idx += 256) {
        int c = idx / RR, r = idx - c*RR;
        float s1 = 0.f, s2 = 0.f;
#pragma unroll 16
        for (int o = 0; o < CC; o++) {
            float g = gs[c*CC + o];
            s1 += g * w1s[o*RR + r];
            s2 += g * w2s[r*CC + o];
        }
        g_F1T[(size_t)r*NCO + n*CC + c] = s1;
        g_F2T[(size_t)r*NCO + n*CC + c] = s2;
    }
}

// ------------------------- K1: channel-attn projections (4 rows/block) -----
__global__ void __launch_bounds__(256) k_attA_proj(const float* __restrict__ x,
                                                   const float* __restrict__ W2) {
    int g0 = blockIdx.x * 4;
    float a1[4][RR], a2[4][RR];
#pragma unroll
    for (int j = 0; j < 4; j++)
#pragma unroll
        for (int r = 0; r < RR; r++) { a1[j][r] = 0.f; a2[j][r] = 0.f; }
    for (int k4 = threadIdx.x * 4; k4 < NT; k4 += 1024) {
        float4 xv[4];
#pragma unroll
        for (int j = 0; j < 4; j++)
            xv[j] = *(const float4*)(x + (size_t)(g0 + j)*NT + k4);
#pragma unroll
        for (int r = 0; r < RR; r++) {
            float4 w1 = *(const float4*)(g_a0W1T + r*NT + k4);
            float4 w2 = *(const float4*)(W2 + r*NT + k4);
#pragma unroll
            for (int j = 0; j < 4; j++) {
                a1[j][r] += xv[j].x*w1.x + xv[j].y*w1.y + xv[j].z*w1.z + xv[j].w*w1.w;
                a2[j][r] += xv[j].x*w2.x + xv[j].y*w2.y + xv[j].z*w2.z + xv[j].w*w2.w;
            }
        }
    }
    __shared__ float red[8][80];
    int lane = threadIdx.x & 31, warp = threadIdx.x >> 5;
#pragma unroll
    for (int j = 0; j < 4; j++)
#pragma unroll
        for (int r = 0; r < RR; r++) {
#pragma unroll
            for (int off = 16; off > 0; off >>= 1) {
                a1[j][r] += __shfl_down_sync(0xffffffffu, a1[j][r], off);
                a2[j][r] += __shfl_down_sync(0xffffffffu, a2[j][r], off);
            }
            if (lane == 0) { red[warp][j*RR + r] = a1[j][r]; red[warp][40 + j*RR + r] = a2[j][r]; }
        }
    __syncthreads();
    int tid = threadIdx.x;
    if (tid < 80) {
        float s = 0.f;
#pragma unroll
        for (int w = 0; w < 8; w++) s += red[w][tid];
        if (tid < 40) {
            int j = tid / RR, r = tid - j*RR;
            g_s1a[(g0 + j)*RR + r] = s;
        } else {
            int k = tid - 40;
            int j = k / RR, r = k - j*RR;
            int bc = g0 + j, b = bc >> 6, c = bc & 63;
            g_s2a[(b*RR + r)*CC + c] = s;
        }
    }
}

// ------------------------- K2: channel-attn softmax (64x64) ----------------
__global__ void k_attA_soft() {
    int b = blockIdx.x >> 6, i = blockIdx.x & 63;
    int j = threadIdx.x;
    float s = 0.f;
#pragma unroll
    for (int r = 0; r < RR; r++) s += g_s1a[(b*CC + i)*RR + r] * g_s2a[(b*RR + r)*CC + j];
    s *= rsqrtf((float)NT);
    __shared__ float sm[CC];
    sm[j] = s; __syncthreads();
    float mx = -1e30f;
    for (int jj = 0; jj < CC; jj++) mx = fmaxf(mx, sm[jj]);
    float e = expf(s - mx);
    __syncthreads();
    sm[j] = e; __syncthreads();
    float sum = 0.f;
    for (int jj = 0; jj < CC; jj++) sum += sm[jj];
    g_att0[(b*CC + i)*CC + j] = e / sum;
}

// ------------------------- K3: x1t = att0 @ xf (fp32 + fp16 copy) ----------
__global__ void __launch_bounds__(256) k_chan_apply(const float* __restrict__ x) {
    int b = blockIdx.y;
    int k0 = blockIdx.x * 64;
    __shared__ float atts[CC][68];
    __shared__ float xfs[CC][64];
    int tid = threadIdx.x;
    for (int e = tid; e < CC*CC; e += 256) {
        int c = e >> 6, j = e & 63;
        atts[j][c] = g_att0[b*CC*CC + e];
    }
    for (int e = tid; e < CC*64; e += 256) {
        int j = e >> 6, kk = e & 63;
        xfs[j][kk] = x[(size_t)(b*CC + j)*NT + k0 + kk];
    }
    __syncthreads();
    int tx = tid & 15, ty = tid >> 4;
    unsigned long long acc[4][2];
#pragma unroll
    for (int i = 0; i < 4; i++) { acc[i][0] = 0ull; acc[i][1] = 0ull; }
#pragma unroll 4
    for (int j = 0; j < CC; j++) {
        float4 a = *(const float4*)&atts[j][ty*4];
        ulonglong2 xv = *(const ulonglong2*)&xfs[j][tx*4];
        unsigned long long d0 = dup2(a.x), d1 = dup2(a.y), d2 = dup2(a.z), d3 = dup2(a.w);
        fma2(acc[0][0], d0, xv.x); fma2(acc[0][1], d0, xv.y);
        fma2(acc[1][0], d1, xv.x); fma2(acc[1][1], d1, xv.y);
        fma2(acc[2][0], d2, xv.x); fma2(acc[2][1], d2, xv.y);
        fma2(acc[3][0], d3, xv.x); fma2(acc[3][1], d3, xv.y);
    }
    int kk0 = k0 + tx*4;
    int n = kk0 / TT, t0 = kk0 - n*TT;     // t0 % 4 == 0, 4 kk share row n
    size_t base = ((size_t)b*NN + n)*CT + t0;
#pragma unroll
    for (int ci = 0; ci < 4; ci++) {
        int c = ty*4 + ci;
        float vx = lo32(acc[ci][0]), vy = hi32(acc[ci][0]);
        float vz = lo32(acc[ci][1]), vw = hi32(acc[ci][1]);
        *(float4*)&g_x1t[base + c*TT] = make_float4(vx, vy, vz, vw);
        union { uint2 u; __half2 h[2]; } q;
        q.h[0] = __floats2half2_rn(vx, vy);
        q.h[1] = __floats2half2_rn(vz, vw);
        *(uint2*)&g_x1h[base + c*TT] = q.u;
    }
}

// ------------------------- K4: graph-attn projections (16 rows/block) ------
__global__ void __launch_bounds__(256) k_gatt_proj(const float* __restrict__ W2) {
    int base = blockIdx.x * 16;
    __shared__ float red[8][2*RR];
    int lane = threadIdx.x & 31, warp = threadIdx.x >> 5;
    for (int row = 0; row < 16; row++) {
        int bn = base + row;
        int b = bn / NN, n = bn - b*NN;
        const float* xf = g_x1t + (size_t)bn * CT;
        float a1[RR], a2[RR];
#pragma unroll
        for (int r = 0; r < RR; r++) { a1[r] = 0.f; a2[r] = 0.f; }
        for (int k4 = threadIdx.x * 4; k4 < CT; k4 += 1024) {
            float4 xv = *(const float4*)(xf + k4);
#pragma unroll
            for (int r = 0; r < RR; r++) {
                float4 w1 = *(const float4*)(g_gW1T + r*CT + k4);
                float4 w2 = *(const float4*)(W2 + r*CT + k4);
                a1[r] += xv.x*w1.x + xv.y*w1.y + xv.z*w1.z + xv.w*w1.w;
                a2[r] += xv.x*w2.x + xv.y*w2.y + xv.z*w2.z + xv.w*w2.w;
            }
        }
#pragma unroll
        for (int r = 0; r < RR; r++) {
#pragma unroll
            for (int off = 16; off > 0; off >>= 1) {
                a1[r] += __shfl_down_sync(0xffffffffu, a1[r], off);
                a2[r] += __shfl_down_sync(0xffffffffu, a2[r], off);
            }
        }
        if (lane == 0) {
#pragma unroll
            for (int r = 0; r < RR; r++) { red[warp][r] = a1[r]; red[warp][RR+r] = a2[r]; }
        }
        __syncthreads();
        if (threadIdx.x < 2*RR) {
            float s = 0.f;
#pragma unroll
            for (int w = 0; w < 8; w++) s += red[w][threadIdx.x];
            if (threadIdx.x < RR) g_s1g[(size_t)bn*RR + threadIdx.x] = s;
            else                  g_s2g[((size_t)b*RR + (threadIdx.x - RR))*NN + n] = s;
        }
        __syncthreads();
    }
}

// ------------------------- K5: graph softmax * A_adj (no-max, fp16 out) ----
__global__ void k_gatt_soft(const float* __restrict__ A_adj) {
    int bi = blockIdx.x;
    int b = bi / NN, i = bi - b*NN;
    __shared__ float sc[NN];
    __shared__ float s1r[RR];
    __shared__ float red[256];
    int tid = threadIdx.x;
    if (tid < RR) s1r[tid] = g_s1g[(size_t)(b*NN + i)*RR + tid];
    __syncthreads();
    float scale = rsqrtf((float)CT);
    float lsum = 0.f;
    for (int j = tid; j < NN; j += 256) {
        float s = 0.f;
#pragma unroll
        for (int r = 0; r < RR; r++) s += s1r[r] * g_s2g[(size_t)(b*RR + r)*NN + j];
        float e = expf(s * scale);
        sc[j] = e;
        lsum += e;
    }
    red[tid] = lsum; __syncthreads();
    for (int off = 128; off > 0; off >>= 1) {
        if (tid < off) red[tid] += red[tid + off];
        __syncthreads();
    }
    float inv = 1.f / red[0];
    for (int j = tid; j < NN; j += 256) {
        g_Agh[((size_t)b*NN + i)*NN + j] = __float2half_rn(sc[j] * inv * A_adj[i*NN + j]);
    }
}

// ------------------------- K7: big GEMM g1 = Ag @ x1t (HFMA2) --------------
#define GTM 128
#define GTN 128
#define GTK 16
__global__ void __launch_bounds__(256) k_gemm() {
    int b  = blockIdx.z;
    int n0 = blockIdx.y * GTM;
    int j0 = blockIdx.x * GTN;
    const __half* A  = g_Agh + (size_t)b*NN*NN;
    const __half* Bm = g_x1h + (size_t)b*NN*CT;
    float*        Cm = g_g1  + (size_t)b*NN*CT;
    __shared__ __half As[2][GTK][GTM + 8];
    __shared__ __half Bs[2][GTK][GTN + 8];
    int tid = threadIdx.x;
    int tx = tid & 15, ty = tid >> 4;
    int an = tid >> 1, ah = (tid & 1) * 8;     // A: row an, k-off {0,8}
    int bk = tid >> 4, bj = (tid & 15) * 8;    // B: k-row bk, col bj
    const uint4 z4 = make_uint4(0u, 0u, 0u, 0u);

    __half2 acch[8][4];
    float accf[8][8];
#pragma unroll
    for (int i = 0; i < 8; i++) {
#pragma unroll
        for (int j = 0; j < 4; j++) acch[i][j] = __float2half2_rn(0.f);
#pragma unroll
        for (int j = 0; j < 8; j++) accf[i][j] = 0.f;
    }

    const int NKT = (NN + GTK - 1) / GTK;      // 63
    {   // preload tile 0 (k chunks always valid at kt=0)
        int n = n0 + an;
        uint4 av = (n < NN) ? *(const uint4*)(A + (size_t)n*NN + ah) : z4;
        const __half* ap = (const __half*)&av;
#pragma unroll
        for (int i = 0; i < 8; i++) As[0][ah + i][an] = ap[i];
        *(uint4*)&Bs[0][bk][bj] = *(const uint4*)(Bm + (size_t)bk*CT + j0 + bj);
    }
    __syncthreads();

    for (int kt = 0; kt < NKT; kt++) {
        int buf = kt & 1;
        uint4 av, bv;
        bool have_next = (kt + 1 < NKT);
        if (have_next) {
            int k0 = (kt + 1) * GTK;
            int n = n0 + an;
            bool va = (n < NN) && (k0 + ah < NN);   // 8-chunk fully valid (1000%8==0)
            av = va ? *(const uint4*)(A + (size_t)n*NN + k0 + ah) : z4;
            bool vb = (k0 + bk < NN);
            bv = vb ? *(const uint4*)(Bm + (size_t)(k0 + bk)*CT + j0 + bj) : z4;
        }
#pragma unroll
        for (int kk = 0; kk < GTK; kk++) {
            uint4 ar = *(const uint4*)&As[buf][kk][ty*8];
            uint4 br = *(const uint4*)&Bs[buf][kk][tx*8];
            const __half*  a8 = (const __half*)&ar;
            const __half2* b2 = (const __half2*)&br;
#pragma unroll
            for (int i = 0; i < 8; i++) {
                __half2 ad = __half2half2(a8[i]);
                acch[i][0] = __hfma2(ad, b2[0], acch[i][0]);
                acch[i][1] = __hfma2(ad, b2[1], acch[i][1]);
                acch[i][2] = __hfma2(ad, b2[2], acch[i][2]);
                acch[i][3] = __hfma2(ad, b2[3], acch[i][3]);
            }
        }
        if ((kt & 3) == 3 || kt == NKT - 1) {   // flush every 64 k-terms -> fp32
#pragma unroll
            for (int i = 0; i < 8; i++)
#pragma unroll
                for (int j = 0; j < 4; j++) {
                    float2 f = __half22float2(acch[i][j]);
                    accf[i][2*j]   += f.x;
                    accf[i][2*j+1] += f.y;
                    acch[i][j] = __float2half2_rn(0.f);
                }
        }
        if (have_next) {
            int nb = buf ^ 1;
            const __half* ap = (const __half*)&av;
#pragma unroll
            for (int i = 0; i < 8; i++) As[nb][ah + i][an] = ap[i];
            *(uint4*)&Bs[nb][bk][bj] = bv;
        }
        __syncthreads();
    }
#pragma unroll
    for (int i = 0; i < 8; i++) {
        int n = n0 + ty*8 + i;
        if (n < NN) {
            float* cp = Cm + (size_t)n*CT + j0 + tx*8;
            *(float4*)cp       = make_float4(accf[i][0], accf[i][1], accf[i][2], accf[i][3]);
            *(float4*)(cp + 4) = make_float4(accf[i][4], accf[i][5], accf[i][6], accf[i][7]);
        }
    }
}

// ------------------------- K8: temporal-attn projections (r-split, 96 blk) -
__global__ void __launch_bounds__(256) k_tatt_proj() {
    int z  = blockIdx.x;
    int rh = z & 1;
    int bt = z >> 1;
    int b  = bt / 6;
    int tg = bt - b*6;
    int t0 = tg * 4;
    const float* g1b = g_g1 + (size_t)b*NN*CT;
    unsigned long long a1p[2][5], a2p[2][5];
#pragma unroll
    for (int p = 0; p < 2; p++)
#pragma unroll
        for (int r = 0; r < 5; r++) { a1p[p][r] = 0ull; a2p[p][r] = 0ull; }

    for (int i4 = threadIdx.x * 4; i4 < NCO; i4 += 1024) {
        int n = i4 >> 6, c0 = i4 & 63;
        const float* gp = g1b + (size_t)n*CT + c0*TT + t0;
        unsigned long long gq[4][2];
#pragma unroll
        for (int j = 0; j < 4; j++) {
            ulonglong2 gv = *(const ulonglong2*)(gp + j*TT);
            gq[j][0] = gv.x; gq[j][1] = gv.y;
        }
#pragma unroll
        for (int r = 0; r < 5; r++) {
            int rr = rh*5 + r;
            float4 f1 = *(const float4*)(g_F1T + (size_t)rr*NCO + i4);
            float4 f2 = *(const float4*)(g_F2T + (size_t)rr*NCO + i4);
            unsigned long long d;
            d = dup2(f1.x); fma2(a1p[0][r], d, gq[0][0]); fma2(a1p[1][r], d, gq[0][1]);
            d = dup2(f1.y); fma2(a1p[0][r], d, gq[1][0]); fma2(a1p[1][r], d, gq[1][1]);
            d = dup2(f1.z); fma2(a1p[0][r], d, gq[2][0]); fma2(a1p[1][r], d, gq[2][1]);
            d = dup2(f1.w); fma2(a1p[0][r], d, gq[3][0]); fma2(a1p[1][r], d, gq[3][1]);
            d = dup2(f2.x); fma2(a2p[0][r], d, gq[0][0]); fma2(a2p[1][r], d, gq[0][1]);
            d = dup2(f2.y); fma2(a2p[0][r], d, gq[1][0]); fma2(a2p[1][r], d, gq[1][1]);
            d = dup2(f2.z); fma2(a2p[0][r], d, gq[2][0]); fma2(a2p[1][r], d, gq[2][1]);
            d = dup2(f2.w); fma2(a2p[0][r], d, gq[3][0]); fma2(a2p[1][r], d, gq[3][1]);
        }
    }
    __shared__ unsigned long long redu[8][20];
    int lane = threadIdx.x & 31, warp = threadIdx.x >> 5;
#pragma unroll
    for (int p = 0; p < 2; p++)
#pragma unroll
        for (int r = 0; r < 5; r++) {
            unsigned long long v1 = a1p[p][r], v2 = a2p[p][r];
#pragma unroll
            for (int off = 16; off > 0; off >>= 1) {
                float l1 = lo32(v1) + __shfl_down_sync(0xffffffffu, lo32(v1), off);
                float h1 = hi32(v1) + __shfl_down_sync(0xffffffffu, hi32(v1), off);
                float l2 = lo32(v2) + __shfl_down_sync(0xffffffffu, lo32(v2), off);
                float h2 = hi32(v2) + __shfl_down_sync(0xffffffffu, hi32(v2), off);
                v1 = pack2(l1, h1); v2 = pack2(l2, h2);
            }
            if (lane == 0) {
                redu[warp][r*2 + p]      = v1;
                redu[warp][10 + r*2 + p] = v2;
            }
        }
    __syncthreads();
    int tid = threadIdx.x;
    if (tid < 20) {
        float slo = 0.f, shi = 0.f;
#pragma unroll
        for (int w = 0; w < 8; w++) {
            unsigned long long v = redu[w][tid];
            slo += lo32(v); shi += hi32(v);
        }
        int mat = tid / 10;
        int rem = tid - mat*10;
        int r = rem >> 1, p = rem & 1;
        int rr = rh*5 + r;
        int t = t0 + 2*p;
        if (mat == 0) {
            g_s1t[(b*TT + t)*RR + rr]     = slo;
            g_s1t[(b*TT + t + 1)*RR + rr] = shi;
        } else {
            g_s2t[(b*RR + rr)*TT + t]     = slo;
            g_s2t[(b*RR + rr)*TT + t + 1] = shi;
        }
    }
}

// ------------------------- K9: temporal softmax (24x24) --------------------
__global__ void k_tatt_soft() {
    int b = blockIdx.x;
    int i = threadIdx.x;
    if (i >= TT) return;
    float sc[TT];
    float scale = rsqrtf((float)NCO);
#pragma unroll
    for (int j = 0; j < TT; j++) {
        float s = 0.f;
#pragma unroll
        for (int r = 0; r < RR; r++) s += g_s1t[(b*TT + i)*RR + r] * g_s2t[(b*RR + r)*TT + j];
        sc[j] = s * scale;
    }
    float mx = -1e30f;
#pragma unroll
    for (int j = 0; j < TT; j++) mx = fmaxf(mx, sc[j]);
    float sum = 0.f;
#pragma unroll
    for (int j = 0; j < TT; j++) { sc[j] = expf(sc[j] - mx); sum += sc[j]; }
    float inv = 1.f / sum;
#pragma unroll
    for (int j = 0; j < TT; j++) g_attT[(b*TT + i)*TT + j] = sc[j] * inv;
}

// ------------------------- K10: fused mix + tatt-apply + convs + res + LN --
__global__ void __launch_bounds__(256) k_final(
        const float* __restrict__ x,
        const float* __restrict__ gcnW,
        const float* __restrict__ c1b,
        const float* __restrict__ c2b,
        const float* __restrict__ rb,
        const float* __restrict__ lng,
        const float* __restrict__ lnb,
        float* __restrict__ out) {
    __shared__ float smB[4*CT];
    __shared__ float at_s[TT*TT];
    __shared__ float mu_s[4][TT], rs_s[4][TT];
    int blk = blockIdx.x;
    int b = blk / 250;
    int n0 = (blk - b*250) * 4;
    int tid = threadIdx.x;
    int u = tid >> 6, o = tid & 63;
    int n = n0 + u;

    {
        const float* src = g_g1 + ((size_t)b*NN + n0)*CT;
        for (int e4 = tid; e4 < CT; e4 += 256)
            *(float4*)&smB[e4*4] = *(const float4*)(src + e4*4);
    }
    for (int e = tid; e < TT*TT; e += 256) {
        int t = e / TT, tp = e - t*TT;
        at_s[tp*TT + t] = g_attT[b*TT*TT + e];
    }
    __syncthreads();

    unsigned long long gmp[12];
#pragma unroll
    for (int k = 0; k < 12; k++) gmp[k] = 0ull;
#pragma unroll 4
    for (int c = 0; c < CC; c++) {
        unsigned long long wd = dup2(__ldg(gcnW + c*CC + o));
        const unsigned long long* pr = (const unsigned long long*)&smB[u*CT + c*TT];
#pragma unroll
        for (int k = 0; k < 12; k++) fma2(gmp[k], wd, pr[k]);
    }
    float gm[TT];
#pragma unroll
    for (int k = 0; k < 12; k++) { gm[2*k] = lo32(gmp[k]); gm[2*k+1] = hi32(gmp[k]); }

    unsigned long long x2p[12];
#pragma unroll
    for (int k = 0; k < 12; k++) x2p[k] = 0ull;
#pragma unroll 4
    for (int tp = 0; tp < TT; tp++) {
        unsigned long long gd = dup2(gm[tp]);
        const unsigned long long* ar = (const unsigned long long*)&at_s[tp*TT];
#pragma unroll
        for (int k = 0; k < 12; k++) fma2(x2p[k], gd, ar[k]);
    }
    __syncthreads();
    {
        unsigned long long* wp = (unsigned long long*)&smB[u*CT + o*TT];
#pragma unroll
        for (int k = 0; k < 12; k++) wp[k] = x2p[k];
    }
    __syncthreads();

    unsigned long long yp[12];
    {
        unsigned long long bias = dup2(__ldg(c1b + o));
#pragma unroll
        for (int k = 0; k < 12; k++) yp[k] = bias;
#pragma unroll 4
        for (int c = 0; c < CC; c++) {
            const unsigned long long* pr = (const unsigned long long*)&smB[u*CT + c*TT];
            unsigned long long w0d = dup2(__ldg(g_w1T + c*CC + o));
            unsigned long long w1d = dup2(__ldg(g_w1T + CC*CC + c*CC + o));
            unsigned long long tp_[12];
#pragma unroll
            for (int k = 0; k < 12; k++) tp_[k] = pr[k];
#pragma unroll
            for (int k = 0; k < 12; k++) fma2(yp[k], w1d, tp_[k]);
            unsigned long long sh = pack2(0.f, lo32(tp_[0]));
            fma2(yp[0], w0d, sh);
#pragma unroll
            for (int k = 1; k < 12; k++) {
                sh = pack2(hi32(tp_[k-1]), lo32(tp_[k]));
                fma2(yp[k], w0d, sh);
            }
        }
    }
    float y1[TT];
#pragma unroll
    for (int k = 0; k < 12; k++) {
        y1[2*k]   = fmaxf(lo32(yp[k]), 0.f);
        y1[2*k+1] = fmaxf(hi32(yp[k]), 0.f);
    }
    __syncthreads();
    {
        float* wp = &smB[u*CT + o*TT];
#pragma unroll
        for (int k = 0; k < 6; k++)
            *(float4*)(wp + 4*k) = make_float4(y1[4*k], y1[4*k+1], y1[4*k+2], y1[4*k+3]);
    }
    __syncthreads();

    unsigned long long vp[12];
    {
        unsigned long long bias = dup2(__ldg(c2b + o));
#pragma unroll
        for (int k = 0; k < 12; k++) vp[k] = bias;
#pragma unroll 4
        for (int c = 0; c < CC; c++) {
            const unsigned long long* pr = (const unsigned long long*)&smB[u*CT + c*TT];
            unsigned long long w0d = dup2(__ldg(g_w2T + c*CC + o));
            unsigned long long w1d = dup2(__ldg(g_w2T + CC*CC + c*CC + o));
            unsigned long long prev = 0ull;
#pragma unroll
            for (int k = 0; k < 12; k++) {
                unsigned long long cur = pr[k];
                fma2(vp[k], w1d, cur);
                fma2(vp[k], w0d, prev);
                prev = cur;
            }
        }
    }
#pragma unroll
    for (int k = 0; k < 12; k++)
        vp[k] = pack2(fmaxf(lo32(vp[k]), 0.f), fmaxf(hi32(vp[k]), 0.f));
    __syncthreads();

    for (int e4 = tid; e4 < CT; e4 += 256) {
        int f = e4 * 4;
        int u2 = f / CT, rem = f - u2*CT;
        int c = rem / TT, t = rem - c*TT;
        *(float4*)&smB[f] = *(const float4*)(x + (size_t)((b*CC + c)*NN + n0 + u2)*TT + t);
    }
    __syncthreads();

#pragma unroll 4
    for (int c = 0; c < CC; c++) {
        const unsigned long long* pr = (const unsigned long long*)&smB[u*CT + c*TT];
        unsigned long long rwd = dup2(__ldg(g_rT + c*CC + o));
#pragma unroll
        for (int k = 0; k < 12; k++) fma2(vp[k], rwd, pr[k]);
    }
    {
        float biasr = __ldg(rb + o);
#pragma unroll
        for (int k = 0; k < 12; k++) {
            float lo = fmaxf(lo32(vp[k]) + biasr, 0.f);
            float hi = fmaxf(hi32(vp[k]) + biasr, 0.f);
            vp[k] = pack2(lo, hi);
        }
    }
    float v[TT];
#pragma unroll
    for (int k = 0; k < 12; k++) { v[2*k] = lo32(vp[k]); v[2*k+1] = hi32(vp[k]); }
    __syncthreads();

    {
        float* wp = &smB[u*CT + o*TT];
#pragma unroll
        for (int k = 0; k < 6; k++)
            *(float4*)(wp + 4*k) = make_float4(v[4*k], v[4*k+1], v[4*k+2], v[4*k+3]);
    }
    __syncthreads();
    if (tid < 96) {
        int ur = tid / TT, tr = tid - ur*TT;
        float S = 0.f, Q = 0.f;
#pragma unroll 8
        for (int oo = 0; oo < CC; oo++) {
            float val = smB[ur*CT + oo*TT + tr];
            S += val; Q += val*val;
        }
        float mu = S * (1.f/CC);
        float var = Q * (1.f/CC) - mu*mu;
        mu_s[ur][tr] = mu;
        rs_s[ur][tr] = rsqrtf(var + 1e-5f);
    }
    __syncthreads();
    {
        float gmul = __ldg(lng + o), badd = __ldg(lnb + o);
        float* op = out + (size_t)((b*CC + o)*NN + n)*TT;
        float res[TT];
#pragma unroll
        for (int t = 0; t < TT; t++)
            res[t] = (v[t] - mu_s[u][t]) * rs_s[u][t] * gmul + badd;
#pragma unroll
        for (int k = 0; k < 6; k++)
            *(float4*)(op + 4*k) = make_float4(res[4*k], res[4*k+1], res[4*k+2], res[4*k+3]);
    }
}

// ------------------------- launch ------------------------------------------
extern "C" void kernel_launch(void* const* d_in, const int* in_sizes, int n_in,
                              void* d_out, int out_size) {
    const float* x     = (const float*)d_in[0];
    const float* A_adj = (const float*)d_in[1];
    const float* a0W1  = (const float*)d_in[2];
    const float* a0W2  = (const float*)d_in[3];
    const float* gW1   = (const float*)d_in[4];
    const float* gW2   = (const float*)d_in[5];
    const float* gcnW  = (const float*)d_in[6];
    const float* tW1   = (const float*)d_in[7];
    const float* tW2   = (const float*)d_in[8];
    const float* c1w   = (const float*)d_in[9];
    const float* c1b   = (const float*)d_in[10];
    const float* c2w   = (const float*)d_in[11];
    const float* c2b   = (const float*)d_in[12];
    const float* resw  = (const float*)d_in[13];
    const float* resb  = (const float*)d_in[14];
    const float* lng   = (const float*)d_in[15];
    const float* lnb   = (const float*)d_in[16];
    float* out = (float*)d_out;

    k_prep<<<1014, 256>>>(a0W1, gW1, c1w, c2w, resw);
    k_fuse<<<NN, 256>>>(gcnW, tW1, tW2);
    k_attA_proj<<<BB*CC/4, 256>>>(x, a0W2);
    k_attA_soft<<<BB*CC, CC>>>();
    k_chan_apply<<<dim3(NT/64, BB), 256>>>(x);
    k_gatt_proj<<<BB*NN/16, 256>>>(gW2);
    k_gatt_soft<<<BB*NN, 256>>>(A_adj);
    k_gemm<<<dim3(CT/GTN, (NN + GTM - 1)/GTM, BB), 256>>>();
    k_tatt_proj<<<BB*6*2, 256>>>();
    k_tatt_soft<<<BB, 32>>>();
    k_final<<<BB*NN/4, 256>>>(x, gcnW, c1b, c2b, resb, lng, lnb, out);
}

// round 13
// speedup vs baseline: 1.2959x; 1.0700x over previous
#include <cuda_runtime.h>
#include <cuda_fp16.h>
#include <math.h>

#define BB 8
#define CC 64
#define NN 1000
#define TT 24
#define RR 10
#define NT 24000     // NN*TT
#define CT 1536      // CC*TT
#define NCO 64000    // NN*CC

// ------------------------- scratch (device globals, no allocs) -------------
__device__ float  g_x1t[BB*NN*CT];        // x1 transposed [b][n][(c*T+t)] fp32
__device__ __half g_x1h[BB*NN*CT];        // fp16 copy for GEMM B
__device__ __half g_Agh[BB*NN*NN];        // gated adjacency fp16 [b][n][m]
__device__ float  g_g1[BB*NN*CT];         // Ag @ x1t  [b][n][(c*T+t)]
__device__ float g_s1a[BB*CC*RR];
__device__ float g_s2a[BB*RR*CC];
__device__ float g_att0[BB*CC*CC];
__device__ float g_s1g[BB*NN*RR];
__device__ float g_s2g[BB*RR*NN];
__device__ float g_s1t[BB*TT*RR];
__device__ float g_s2t[BB*RR*TT];
__device__ float g_attT[BB*TT*TT];
// transposed / fused weights
__device__ float g_a0W1T[RR*NT];
__device__ float g_gW1T[RR*CT];
__device__ float g_F1T[RR*NCO];
__device__ float g_F2T[RR*NCO];
__device__ float g_w1T[2*CC*CC];
__device__ float g_w2T[2*CC*CC];
__device__ float g_rT[CC*CC];
// half weights for k_final fast stages
__device__ __half g_gWh[CC*CC];           // gcn_W [c][o]
__device__ __half g_w1h[2*CC*CC];         // conv1 [tap][c][o]
__device__ __half g_w2h[2*CC*CC];         // conv2 [tap][c][o]

// ------------------------- f32x2 helpers -----------------------------------
__device__ __forceinline__ unsigned long long dup2(float v) {
    unsigned long long r; unsigned u = __float_as_uint(v);
    asm("mov.b64 %0, {%1, %1};" : "=l"(r) : "r"(u));
    return r;
}
__device__ __forceinline__ unsigned long long pack2(float lo, float hi) {
    unsigned long long r;
    asm("mov.b64 %0, {%1, %2};" : "=l"(r) : "r"(__float_as_uint(lo)), "r"(__float_as_uint(hi)));
    return r;
}
__device__ __forceinline__ void fma2(unsigned long long& d,
                                     unsigned long long a, unsigned long long b) {
    asm("fma.rn.f32x2 %0, %1, %2, %0;" : "+l"(d) : "l"(a), "l"(b));
}
__device__ __forceinline__ float lo32(unsigned long long v) {
    return __uint_as_float((unsigned)v);
}
__device__ __forceinline__ float hi32(unsigned long long v) {
    return __uint_as_float((unsigned)(v >> 32));
}

// ------------------------- K0: weight prep (transposes + half) -------------
__global__ void k_prep(const float* __restrict__ a0W1, const float* __restrict__ gW1,
                       const float* __restrict__ c1w, const float* __restrict__ c2w,
                       const float* __restrict__ rw, const float* __restrict__ gcnW) {
    int e = blockIdx.x * 256 + threadIdx.x;
    if (e < NT*RR)  { int k = e/RR, r = e - k*RR; g_a0W1T[r*NT + k] = a0W1[e]; return; }
    e -= NT*RR;
    if (e < CT*RR)  { int k = e/RR, r = e - k*RR; g_gW1T[r*CT + k] = gW1[e]; return; }
    e -= CT*RR;
    if (e < CC*CC) {
        int o = e >> 6, c = e & 63;
        float w10 = c1w[e*2 + 0], w11 = c1w[e*2 + 1];
        float w20 = c2w[e*2 + 0], w21 = c2w[e*2 + 1];
        g_w1T[c*CC + o]         = w10;
        g_w1T[CC*CC + c*CC + o] = w11;
        g_w2T[c*CC + o]         = w20;
        g_w2T[CC*CC + c*CC + o] = w21;
        g_rT[c*CC + o]          = rw[e];
        g_w1h[c*CC + o]         = __float2half_rn(w10);
        g_w1h[CC*CC + c*CC + o] = __float2half_rn(w11);
        g_w2h[c*CC + o]         = __float2half_rn(w20);
        g_w2h[CC*CC + c*CC + o] = __float2half_rn(w21);
        g_gWh[e]                = __float2half_rn(gcnW[e]);
    }
}

// ------------------------- K0b: fuse gcn_W into tatt weights ---------------
__global__ void k_fuse(const float* __restrict__ gcnW, const float* __restrict__ tW1,
                       const float* __restrict__ tW2) {
    int n = blockIdx.x;
    __shared__ float gs[CC*CC];
    __shared__ float w1s[CC*RR];
    __shared__ float w2s[RR*CC];
    int tid = threadIdx.x;
    for (int e = tid; e < CC*CC; e += 256) gs[e] = gcnW[e];
    for (int e = tid; e < CC*RR; e += 256) w1s[e] = tW1[(size_t)(n*CC)*RR + e];
    for (int e = tid; e < RR*CC; e += 256) {
        int r = e / CC, o = e - r*CC;
        w2s[e] = tW2[(size_t)r*NCO + n*CC + o];
    }
    __syncthreads();
    for (int idx = tid; idx < CC*RR; idx += 256) {
        int c = idx / RR, r = idx - c*RR;
        float s1 = 0.f, s2 = 0.f;
#pragma unroll 16
        for (int o = 0; o < CC; o++) {
            float g = gs[c*CC + o];
            s1 += g * w1s[o*RR + r];
            s2 += g * w2s[r*CC + o];
        }
        g_F1T[(size_t)r*NCO + n*CC + c] = s1;
        g_F2T[(size_t)r*NCO + n*CC + c] = s2;
    }
}

// ------------------------- K1: channel-attn projections (4 rows/block) -----
__global__ void __launch_bounds__(256) k_attA_proj(const float* __restrict__ x,
                                                   const float* __restrict__ W2) {
    int g0 = blockIdx.x * 4;
    float a1[4][RR], a2[4][RR];
#pragma unroll
    for (int j = 0; j < 4; j++)
#pragma unroll
        for (int r = 0; r < RR; r++) { a1[j][r] = 0.f; a2[j][r] = 0.f; }
    for (int k4 = threadIdx.x * 4; k4 < NT; k4 += 1024) {
        float4 xv[4];
#pragma unroll
        for (int j = 0; j < 4; j++)
            xv[j] = *(const float4*)(x + (size_t)(g0 + j)*NT + k4);
#pragma unroll
        for (int r = 0; r < RR; r++) {
            float4 w1 = *(const float4*)(g_a0W1T + r*NT + k4);
            float4 w2 = *(const float4*)(W2 + r*NT + k4);
#pragma unroll
            for (int j = 0; j < 4; j++) {
                a1[j][r] += xv[j].x*w1.x + xv[j].y*w1.y + xv[j].z*w1.z + xv[j].w*w1.w;
                a2[j][r] += xv[j].x*w2.x + xv[j].y*w2.y + xv[j].z*w2.z + xv[j].w*w2.w;
            }
        }
    }
    __shared__ float red[8][80];
    int lane = threadIdx.x & 31, warp = threadIdx.x >> 5;
#pragma unroll
    for (int j = 0; j < 4; j++)
#pragma unroll
        for (int r = 0; r < RR; r++) {
#pragma unroll
            for (int off = 16; off > 0; off >>= 1) {
                a1[j][r] += __shfl_down_sync(0xffffffffu, a1[j][r], off);
                a2[j][r] += __shfl_down_sync(0xffffffffu, a2[j][r], off);
            }
            if (lane == 0) { red[warp][j*RR + r] = a1[j][r]; red[warp][40 + j*RR + r] = a2[j][r]; }
        }
    __syncthreads();
    int tid = threadIdx.x;
    if (tid < 80) {
        float s = 0.f;
#pragma unroll
        for (int w = 0; w < 8; w++) s += red[w][tid];
        if (tid < 40) {
            int j = tid / RR, r = tid - j*RR;
            g_s1a[(g0 + j)*RR + r] = s;
        } else {
            int k = tid - 40;
            int j = k / RR, r = k - j*RR;
            int bc = g0 + j, b = bc >> 6, c = bc & 63;
            g_s2a[(b*RR + r)*CC + c] = s;
        }
    }
}

// ------------------------- K2: channel-attn softmax (64x64) ----------------
__global__ void k_attA_soft() {
    int b = blockIdx.x >> 6, i = blockIdx.x & 63;
    int j = threadIdx.x;
    float s = 0.f;
#pragma unroll
    for (int r = 0; r < RR; r++) s += g_s1a[(b*CC + i)*RR + r] * g_s2a[(b*RR + r)*CC + j];
    s *= rsqrtf((float)NT);
    __shared__ float sm[CC];
    sm[j] = s; __syncthreads();
    float mx = -1e30f;
    for (int jj = 0; jj < CC; jj++) mx = fmaxf(mx, sm[jj]);
    float e = expf(s - mx);
    __syncthreads();
    sm[j] = e; __syncthreads();
    float sum = 0.f;
    for (int jj = 0; jj < CC; jj++) sum += sm[jj];
    g_att0[(b*CC + i)*CC + j] = e / sum;
}

// ------------------------- K3: x1t = att0 @ xf (fp32 + fp16 copy) ----------
__global__ void __launch_bounds__(256) k_chan_apply(const float* __restrict__ x) {
    int b = blockIdx.y;
    int k0 = blockIdx.x * 64;
    __shared__ float atts[CC][68];
    __shared__ float xfs[CC][64];
    int tid = threadIdx.x;
    for (int e = tid; e < CC*CC; e += 256) {
        int c = e >> 6, j = e & 63;
        atts[j][c] = g_att0[b*CC*CC + e];
    }
    for (int e = tid; e < CC*64; e += 256) {
        int j = e >> 6, kk = e & 63;
        xfs[j][kk] = x[(size_t)(b*CC + j)*NT + k0 + kk];
    }
    __syncthreads();
    int tx = tid & 15, ty = tid >> 4;
    unsigned long long acc[4][2];
#pragma unroll
    for (int i = 0; i < 4; i++) { acc[i][0] = 0ull; acc[i][1] = 0ull; }
#pragma unroll 4
    for (int j = 0; j < CC; j++) {
        float4 a = *(const float4*)&atts[j][ty*4];
        ulonglong2 xv = *(const ulonglong2*)&xfs[j][tx*4];
        unsigned long long d0 = dup2(a.x), d1 = dup2(a.y), d2 = dup2(a.z), d3 = dup2(a.w);
        fma2(acc[0][0], d0, xv.x); fma2(acc[0][1], d0, xv.y);
        fma2(acc[1][0], d1, xv.x); fma2(acc[1][1], d1, xv.y);
        fma2(acc[2][0], d2, xv.x); fma2(acc[2][1], d2, xv.y);
        fma2(acc[3][0], d3, xv.x); fma2(acc[3][1], d3, xv.y);
    }
    int kk0 = k0 + tx*4;
    int n = kk0 / TT, t0 = kk0 - n*TT;     // t0 % 4 == 0, 4 kk share row n
    size_t base = ((size_t)b*NN + n)*CT + t0;
#pragma unroll
    for (int ci = 0; ci < 4; ci++) {
        int c = ty*4 + ci;
        float vx = lo32(acc[ci][0]), vy = hi32(acc[ci][0]);
        float vz = lo32(acc[ci][1]), vw = hi32(acc[ci][1]);
        *(float4*)&g_x1t[base + c*TT] = make_float4(vx, vy, vz, vw);
        union { uint2 u; __half2 h[2]; } q;
        q.h[0] = __floats2half2_rn(vx, vy);
        q.h[1] = __floats2half2_rn(vz, vw);
        *(uint2*)&g_x1h[base + c*TT] = q.u;
    }
}

// ------------------------- K4: graph-attn projections (16 rows/block) ------
__global__ void __launch_bounds__(256) k_gatt_proj(const float* __restrict__ W2) {
    int base = blockIdx.x * 16;
    __shared__ float red[8][2*RR];
    int lane = threadIdx.x & 31, warp = threadIdx.x >> 5;
    for (int row = 0; row < 16; row++) {
        int bn = base + row;
        int b = bn / NN, n = bn - b*NN;
        const float* xf = g_x1t + (size_t)bn * CT;
        float a1[RR], a2[RR];
#pragma unroll
        for (int r = 0; r < RR; r++) { a1[r] = 0.f; a2[r] = 0.f; }
        for (int k4 = threadIdx.x * 4; k4 < CT; k4 += 1024) {
            float4 xv = *(const float4*)(xf + k4);
#pragma unroll
            for (int r = 0; r < RR; r++) {
                float4 w1 = *(const float4*)(g_gW1T + r*CT + k4);
                float4 w2 = *(const float4*)(W2 + r*CT + k4);
                a1[r] += xv.x*w1.x + xv.y*w1.y + xv.z*w1.z + xv.w*w1.w;
                a2[r] += xv.x*w2.x + xv.y*w2.y + xv.z*w2.z + xv.w*w2.w;
            }
        }
#pragma unroll
        for (int r = 0; r < RR; r++) {
#pragma unroll
            for (int off = 16; off > 0; off >>= 1) {
                a1[r] += __shfl_down_sync(0xffffffffu, a1[r], off);
                a2[r] += __shfl_down_sync(0xffffffffu, a2[r], off);
            }
        }
        if (lane == 0) {
#pragma unroll
            for (int r = 0; r < RR; r++) { red[warp][r] = a1[r]; red[warp][RR+r] = a2[r]; }
        }
        __syncthreads();
        if (threadIdx.x < 2*RR) {
            float s = 0.f;
#pragma unroll
            for (int w = 0; w < 8; w++) s += red[w][threadIdx.x];
            if (threadIdx.x < RR) g_s1g[(size_t)bn*RR + threadIdx.x] = s;
            else                  g_s2g[((size_t)b*RR + (threadIdx.x - RR))*NN + n] = s;
        }
        __syncthreads();
    }
}

// ------------------------- K5: graph softmax * A_adj (no-max, fp16 out) ----
__global__ void k_gatt_soft(const float* __restrict__ A_adj) {
    int bi = blockIdx.x;
    int b = bi / NN, i = bi - b*NN;
    __shared__ float sc[NN];
    __shared__ float s1r[RR];
    __shared__ float red[256];
    int tid = threadIdx.x;
    if (tid < RR) s1r[tid] = g_s1g[(size_t)(b*NN + i)*RR + tid];
    __syncthreads();
    float scale = rsqrtf((float)CT);
    float lsum = 0.f;
    for (int j = tid; j < NN; j += 256) {
        float s = 0.f;
#pragma unroll
        for (int r = 0; r < RR; r++) s += s1r[r] * g_s2g[(size_t)(b*RR + r)*NN + j];
        float e = expf(s * scale);
        sc[j] = e;
        lsum += e;
    }
    red[tid] = lsum; __syncthreads();
    for (int off = 128; off > 0; off >>= 1) {
        if (tid < off) red[tid] += red[tid + off];
        __syncthreads();
    }
    float inv = 1.f / red[0];
    for (int j = tid; j < NN; j += 256) {
        g_Agh[((size_t)b*NN + i)*NN + j] = __float2half_rn(sc[j] * inv * A_adj[i*NN + j]);
    }
}

// ------------------------- K7: big GEMM g1 = Ag @ x1t (HFMA2, 2 CTA/SM) ----
#define GTM 128
#define GTN 128
#define GTK 16
__global__ void __launch_bounds__(256, 2) k_gemm() {
    int b  = blockIdx.z;
    int n0 = blockIdx.y * GTM;
    int j0 = blockIdx.x * GTN;
    const __half* A  = g_Agh + (size_t)b*NN*NN;
    const __half* Bm = g_x1h + (size_t)b*NN*CT;
    float*        Cm = g_g1  + (size_t)b*NN*CT;
    __shared__ __half As[2][GTK][GTM + 8];
    __shared__ __half Bs[2][GTK][GTN + 8];
    int tid = threadIdx.x;
    int tx = tid & 15, ty = tid >> 4;
    int an = tid >> 1, ah = (tid & 1) * 8;
    int bk = tid >> 4, bj = (tid & 15) * 8;
    const uint4 z4 = make_uint4(0u, 0u, 0u, 0u);

    __half2 acch[8][4];
    float accf[8][8];
#pragma unroll
    for (int i = 0; i < 8; i++) {
#pragma unroll
        for (int j = 0; j < 4; j++) acch[i][j] = __float2half2_rn(0.f);
#pragma unroll
        for (int j = 0; j < 8; j++) accf[i][j] = 0.f;
    }

    const int NKT = (NN + GTK - 1) / GTK;      // 63
    {
        int n = n0 + an;
        uint4 av = (n < NN) ? *(const uint4*)(A + (size_t)n*NN + ah) : z4;
        const __half* ap = (const __half*)&av;
#pragma unroll
        for (int i = 0; i < 8; i++) As[0][ah + i][an] = ap[i];
        *(uint4*)&Bs[0][bk][bj] = *(const uint4*)(Bm + (size_t)bk*CT + j0 + bj);
    }
    __syncthreads();

    for (int kt = 0; kt < NKT; kt++) {
        int buf = kt & 1;
        uint4 av, bv;
        bool have_next = (kt + 1 < NKT);
        if (have_next) {
            int k0 = (kt + 1) * GTK;
            int n = n0 + an;
            bool va = (n < NN) && (k0 + ah < NN);
            av = va ? *(const uint4*)(A + (size_t)n*NN + k0 + ah) : z4;
            bool vb = (k0 + bk < NN);
            bv = vb ? *(const uint4*)(Bm + (size_t)(k0 + bk)*CT + j0 + bj) : z4;
        }
#pragma unroll
        for (int kk = 0; kk < GTK; kk++) {
            uint4 ar = *(const uint4*)&As[buf][kk][ty*8];
            uint4 br = *(const uint4*)&Bs[buf][kk][tx*8];
            const __half*  a8 = (const __half*)&ar;
            const __half2* b2 = (const __half2*)&br;
#pragma unroll
            for (int i = 0; i < 8; i++) {
                __half2 ad = __half2half2(a8[i]);
                acch[i][0] = __hfma2(ad, b2[0], acch[i][0]);
                acch[i][1] = __hfma2(ad, b2[1], acch[i][1]);
                acch[i][2] = __hfma2(ad, b2[2], acch[i][2]);
                acch[i][3] = __hfma2(ad, b2[3], acch[i][3]);
            }
        }
        if ((kt & 3) == 3 || kt == NKT - 1) {
#pragma unroll
            for (int i = 0; i < 8; i++)
#pragma unroll
                for (int j = 0; j < 4; j++) {
                    float2 f = __half22float2(acch[i][j]);
                    accf[i][2*j]   += f.x;
                    accf[i][2*j+1] += f.y;
                    acch[i][j] = __float2half2_rn(0.f);
                }
        }
        if (have_next) {
            int nb = buf ^ 1;
            const __half* ap = (const __half*)&av;
#pragma unroll
            for (int i = 0; i < 8; i++) As[nb][ah + i][an] = ap[i];
            *(uint4*)&Bs[nb][bk][bj] = bv;
        }
        __syncthreads();
    }
#pragma unroll
    for (int i = 0; i < 8; i++) {
        int n = n0 + ty*8 + i;
        if (n < NN) {
            float* cp = Cm + (size_t)n*CT + j0 + tx*8;
            *(float4*)cp       = make_float4(accf[i][0], accf[i][1], accf[i][2], accf[i][3]);
            *(float4*)(cp + 4) = make_float4(accf[i][4], accf[i][5], accf[i][6], accf[i][7]);
        }
    }
}

// ------------------------- K8: temporal-attn projections (r-split, 96 blk) -
__global__ void __launch_bounds__(256) k_tatt_proj() {
    int z  = blockIdx.x;
    int rh = z & 1;
    int bt = z >> 1;
    int b  = bt / 6;
    int tg = bt - b*6;
    int t0 = tg * 4;
    const float* g1b = g_g1 + (size_t)b*NN*CT;
    unsigned long long a1p[2][5], a2p[2][5];
#pragma unroll
    for (int p = 0; p < 2; p++)
#pragma unroll
        for (int r = 0; r < 5; r++) { a1p[p][r] = 0ull; a2p[p][r] = 0ull; }

    for (int i4 = threadIdx.x * 4; i4 < NCO; i4 += 1024) {
        int n = i4 >> 6, c0 = i4 & 63;
        const float* gp = g1b + (size_t)n*CT + c0*TT + t0;
        unsigned long long gq[4][2];
#pragma unroll
        for (int j = 0; j < 4; j++) {
            ulonglong2 gv = *(const ulonglong2*)(gp + j*TT);
            gq[j][0] = gv.x; gq[j][1] = gv.y;
        }
#pragma unroll
        for (int r = 0; r < 5; r++) {
            int rr = rh*5 + r;
            float4 f1 = *(const float4*)(g_F1T + (size_t)rr*NCO + i4);
            float4 f2 = *(const float4*)(g_F2T + (size_t)rr*NCO + i4);
            unsigned long long d;
            d = dup2(f1.x); fma2(a1p[0][r], d, gq[0][0]); fma2(a1p[1][r], d, gq[0][1]);
            d = dup2(f1.y); fma2(a1p[0][r], d, gq[1][0]); fma2(a1p[1][r], d, gq[1][1]);
            d = dup2(f1.z); fma2(a1p[0][r], d, gq[2][0]); fma2(a1p[1][r], d, gq[2][1]);
            d = dup2(f1.w); fma2(a1p[0][r], d, gq[3][0]); fma2(a1p[1][r], d, gq[3][1]);
            d = dup2(f2.x); fma2(a2p[0][r], d, gq[0][0]); fma2(a2p[1][r], d, gq[0][1]);
            d = dup2(f2.y); fma2(a2p[0][r], d, gq[1][0]); fma2(a2p[1][r], d, gq[1][1]);
            d = dup2(f2.z); fma2(a2p[0][r], d, gq[2][0]); fma2(a2p[1][r], d, gq[2][1]);
            d = dup2(f2.w); fma2(a2p[0][r], d, gq[3][0]); fma2(a2p[1][r], d, gq[3][1]);
        }
    }
    __shared__ unsigned long long redu[8][20];
    int lane = threadIdx.x & 31, warp = threadIdx.x >> 5;
#pragma unroll
    for (int p = 0; p < 2; p++)
#pragma unroll
        for (int r = 0; r < 5; r++) {
            unsigned long long v1 = a1p[p][r], v2 = a2p[p][r];
#pragma unroll
            for (int off = 16; off > 0; off >>= 1) {
                float l1 = lo32(v1) + __shfl_down_sync(0xffffffffu, lo32(v1), off);
                float h1 = hi32(v1) + __shfl_down_sync(0xffffffffu, hi32(v1), off);
                float l2 = lo32(v2) + __shfl_down_sync(0xffffffffu, lo32(v2), off);
                float h2 = hi32(v2) + __shfl_down_sync(0xffffffffu, hi32(v2), off);
                v1 = pack2(l1, h1); v2 = pack2(l2, h2);
            }
            if (lane == 0) {
                redu[warp][r*2 + p]      = v1;
                redu[warp][10 + r*2 + p] = v2;
            }
        }
    __syncthreads();
    int tid = threadIdx.x;
    if (tid < 20) {
        float slo = 0.f, shi = 0.f;
#pragma unroll
        for (int w = 0; w < 8; w++) {
            unsigned long long v = redu[w][tid];
            slo += lo32(v); shi += hi32(v);
        }
        int mat = tid / 10;
        int rem = tid - mat*10;
        int r = rem >> 1, p = rem & 1;
        int rr = rh*5 + r;
        int t = t0 + 2*p;
        if (mat == 0) {
            g_s1t[(b*TT + t)*RR + rr]     = slo;
            g_s1t[(b*TT + t + 1)*RR + rr] = shi;
        } else {
            g_s2t[(b*RR + rr)*TT + t]     = slo;
            g_s2t[(b*RR + rr)*TT + t + 1] = shi;
        }
    }
}

// ------------------------- K9: temporal softmax (24x24) --------------------
__global__ void k_tatt_soft() {
    int b = blockIdx.x;
    int i = threadIdx.x;
    if (i >= TT) return;
    float sc[TT];
    float scale = rsqrtf((float)NCO);
#pragma unroll
    for (int j = 0; j < TT; j++) {
        float s = 0.f;
#pragma unroll
        for (int r = 0; r < RR; r++) s += g_s1t[(b*TT + i)*RR + r] * g_s2t[(b*RR + r)*TT + j];
        sc[j] = s * scale;
    }
    float mx = -1e30f;
#pragma unroll
    for (int j = 0; j < TT; j++) mx = fmaxf(mx, sc[j]);
    float sum = 0.f;
#pragma unroll
    for (int j = 0; j < TT; j++) { sc[j] = expf(sc[j] - mx); sum += sc[j]; }
    float inv = 1.f / sum;
#pragma unroll
    for (int j = 0; j < TT; j++) g_attT[(b*TT + i)*TT + j] = sc[j] * inv;
}

// ------------------------- K10: fused mix+tatt+convs (half2) + res+LN (f32) -
__global__ void __launch_bounds__(256) k_final(
        const float* __restrict__ x,
        const float* __restrict__ c1b,
        const float* __restrict__ c2b,
        const float* __restrict__ rb,
        const float* __restrict__ lng,
        const float* __restrict__ lnb,
        float* __restrict__ out) {
    __shared__ float smB[4*CT];                // half stages alias onto this
    __shared__ __half at_h[TT*TT];             // transposed attT, fp16
    __shared__ float mu_s[4][TT], rs_s[4][TT];
    __half* smH = (__half*)smB;
    int blk = blockIdx.x;
    int b = blk / 250;
    int n0 = (blk - b*250) * 4;
    int tid = threadIdx.x;
    int u = tid >> 6, o = tid & 63;
    int n = n0 + u;
    const __half2 hz = __float2half2_rn(0.f);

    // load g1 -> half smem; attT^T -> half
    {
        const float* src = g_g1 + ((size_t)b*NN + n0)*CT;
        for (int e4 = tid; e4 < CT; e4 += 256) {
            float4 v = *(const float4*)(src + e4*4);
            union { uint2 u2; __half2 h[2]; } q;
            q.h[0] = __floats2half2_rn(v.x, v.y);
            q.h[1] = __floats2half2_rn(v.z, v.w);
            *(uint2*)&smH[e4*4] = q.u2;
        }
    }
    for (int e = tid; e < TT*TT; e += 256) {
        int t = e / TT, tp = e - t*TT;
        at_h[tp*TT + t] = __float2half_rn(g_attT[b*TT*TT + e]);
    }
    __syncthreads();

    // ---- stage 0: gcn mix (half2) ----
    __half2 gmp[12];
#pragma unroll
    for (int k = 0; k < 12; k++) gmp[k] = hz;
#pragma unroll 4
    for (int c = 0; c < CC; c++) {
        __half2 wd = __half2half2(g_gWh[c*CC + o]);
        const __half2* pr = (const __half2*)(smH + u*CT + c*TT);
#pragma unroll
        for (int k = 0; k < 12; k++) gmp[k] = __hfma2(wd, pr[k], gmp[k]);
    }

    // ---- stage A: temporal attention apply (half2) ----
    __half2 x2p[12];
#pragma unroll
    for (int k = 0; k < 12; k++) x2p[k] = hz;
#pragma unroll 4
    for (int tp = 0; tp < TT; tp++) {
        __half gv = (tp & 1) ? __high2half(gmp[tp >> 1]) : __low2half(gmp[tp >> 1]);
        __half2 gd = __half2half2(gv);
        const __half2* ar = (const __half2*)(at_h + tp*TT);
#pragma unroll
        for (int k = 0; k < 12; k++) x2p[k] = __hfma2(gd, ar[k], x2p[k]);
    }
    __syncthreads();                            // stage-0 reads done
    {
        __half2* wp = (__half2*)(smH + u*CT + o*TT);
#pragma unroll
        for (int k = 0; k < 12; k++) wp[k] = x2p[k];
    }
    __syncthreads();

    // ---- conv1 (d=1, half2; bias added in fp32 after) ----
    __half2 yp[12];
#pragma unroll
    for (int k = 0; k < 12; k++) yp[k] = hz;
#pragma unroll 4
    for (int c = 0; c < CC; c++) {
        const __half2* pr = (const __half2*)(smH + u*CT + c*TT);
        __half2 w0d = __half2half2(g_w1h[c*CC + o]);
        __half2 w1d = __half2half2(g_w1h[CC*CC + c*CC + o]);
        __half2 tp_[12];
#pragma unroll
        for (int k = 0; k < 12; k++) tp_[k] = pr[k];
#pragma unroll
        for (int k = 0; k < 12; k++) yp[k] = __hfma2(w1d, tp_[k], yp[k]);
        __half2 sh = __halves2half2(__float2half_rn(0.f), __low2half(tp_[0]));
        yp[0] = __hfma2(w0d, sh, yp[0]);
#pragma unroll
        for (int k = 1; k < 12; k++) {
            sh = __halves2half2(__high2half(tp_[k-1]), __low2half(tp_[k]));
            yp[k] = __hfma2(w0d, sh, yp[k]);
        }
    }
    // bias + relu in fp32, re-round to half
    __half2 y1h[12];
    {
        float b1 = __ldg(c1b + o);
#pragma unroll
        for (int k = 0; k < 12; k++) {
            float2 f = __half22float2(yp[k]);
            y1h[k] = __floats2half2_rn(fmaxf(f.x + b1, 0.f), fmaxf(f.y + b1, 0.f));
        }
    }
    __syncthreads();                            // conv1 reads done
    {
        __half2* wp = (__half2*)(smH + u*CT + o*TT);
#pragma unroll
        for (int k = 0; k < 12; k++) wp[k] = y1h[k];
    }
    __syncthreads();

    // ---- conv2 (d=2, half2, pair-aligned shift) ----
    __half2 vph[12];
#pragma unroll
    for (int k = 0; k < 12; k++) vph[k] = hz;
#pragma unroll 4
    for (int c = 0; c < CC; c++) {
        const __half2* pr = (const __half2*)(smH + u*CT + c*TT);
        __half2 w0d = __half2half2(g_w2h[c*CC + o]);
        __half2 w1d = __half2half2(g_w2h[CC*CC + c*CC + o]);
        __half2 prev = hz;
#pragma unroll
        for (int k = 0; k < 12; k++) {
            __half2 cur = pr[k];
            vph[k] = __hfma2(w1d, cur, vph[k]);
            vph[k] = __hfma2(w0d, prev, vph[k]);
            prev = cur;
        }
    }
    float v[TT];
    {
        float b2 = __ldg(c2b + o);
#pragma unroll
        for (int k = 0; k < 12; k++) {
            float2 f = __half22float2(vph[k]);
            v[2*k]   = fmaxf(f.x + b2, 0.f);
            v[2*k+1] = fmaxf(f.y + b2, 0.f);
        }
    }
    __syncthreads();                            // conv2 reads done

    // ---- load original x (fp32) into smB ----
    for (int e4 = tid; e4 < CT; e4 += 256) {
        int f = e4 * 4;
        int u2 = f / CT, rem = f - u2*CT;
        int c = rem / TT, t = rem - c*TT;
        *(float4*)&smB[f] = *(const float4*)(x + (size_t)((b*CC + c)*NN + n0 + u2)*TT + t);
    }
    __syncthreads();

    // ---- residual 1x1 + relu (exact fp32) ----
    unsigned long long vp[12];
#pragma unroll
    for (int k = 0; k < 12; k++) vp[k] = pack2(v[2*k], v[2*k+1]);
#pragma unroll 4
    for (int c = 0; c < CC; c++) {
        const unsigned long long* pr = (const unsigned long long*)&smB[u*CT + c*TT];
        unsigned long long rwd = dup2(__ldg(g_rT + c*CC + o));
#pragma unroll
        for (int k = 0; k < 12; k++) fma2(vp[k], rwd, pr[k]);
    }
    {
        float biasr = __ldg(rb + o);
#pragma unroll
        for (int k = 0; k < 12; k++) {
            float lo = fmaxf(lo32(vp[k]) + biasr, 0.f);
            float hi = fmaxf(hi32(vp[k]) + biasr, 0.f);
            v[2*k] = lo; v[2*k+1] = hi;
        }
    }
    __syncthreads();                            // residual reads done

    // ---- LayerNorm over o (64) per (u,t) (fp32) ----
    {
        float* wp = &smB[u*CT + o*TT];
#pragma unroll
        for (int k = 0; k < 6; k++)
            *(float4*)(wp + 4*k) = make_float4(v[4*k], v[4*k+1], v[4*k+2], v[4*k+3]);
    }
    __syncthreads();
    if (tid < 96) {
        int ur = tid / TT, tr = tid - ur*TT;
        float S = 0.f, Q = 0.f;
#pragma unroll 8
        for (int oo = 0; oo < CC; oo++) {
            float val = smB[ur*CT + oo*TT + tr];
            S += val; Q += val*val;
        }
        float mu = S * (1.f/CC);
        float var = Q * (1.f/CC) - mu*mu;
        mu_s[ur][tr] = mu;
        rs_s[ur][tr] = rsqrtf(var + 1e-5f);
    }
    __syncthreads();
    {
        float gmul = __ldg(lng + o), badd = __ldg(lnb + o);
        float* op = out + (size_t)((b*CC + o)*NN + n)*TT;
        float res[TT];
#pragma unroll
        for (int t = 0; t < TT; t++)
            res[t] = (v[t] - mu_s[u][t]) * rs_s[u][t] * gmul + badd;
#pragma unroll
        for (int k = 0; k < 6; k++)
            *(float4*)(op + 4*k) = make_float4(res[4*k], res[4*k+1], res[4*k+2], res[4*k+3]);
    }
}

// ------------------------- launch ------------------------------------------
extern "C" void kernel_launch(void* const* d_in, const int* in_sizes, int n_in,
                              void* d_out, int out_size) {
    const float* x     = (const float*)d_in[0];
    const float* A_adj = (const float*)d_in[1];
    const float* a0W1  = (const float*)d_in[2];
    const float* a0W2  = (const float*)d_in[3];
    const float* gW1   = (const float*)d_in[4];
    const float* gW2   = (const float*)d_in[5];
    const float* gcnW  = (const float*)d_in[6];
    const float* tW1   = (const float*)d_in[7];
    const float* tW2   = (const float*)d_in[8];
    const float* c1w   = (const float*)d_in[9];
    const float* c1b   = (const float*)d_in[10];
    const float* c2w   = (const float*)d_in[11];
    const float* c2b   = (const float*)d_in[12];
    const float* resw  = (const float*)d_in[13];
    const float* resb  = (const float*)d_in[14];
    const float* lng   = (const float*)d_in[15];
    const float* lnb   = (const float*)d_in[16];
    float* out = (float*)d_out;

    k_prep<<<1014, 256>>>(a0W1, gW1, c1w, c2w, resw, gcnW);
    k_fuse<<<NN, 256>>>(gcnW, tW1, tW2);
    k_attA_proj<<<BB*CC/4, 256>>>(x, a0W2);
    k_attA_soft<<<BB*CC, CC>>>();
    k_chan_apply<<<dim3(NT/64, BB), 256>>>(x);
    k_gatt_proj<<<BB*NN/16, 256>>>(gW2);
    k_gatt_soft<<<BB*NN, 256>>>(A_adj);
    k_gemm<<<dim3(CT/GTN, (NN + GTM - 1)/GTM, BB), 256>>>();
    k_tatt_proj<<<BB*6*2, 256>>>();
    k_tatt_soft<<<BB, 32>>>();
    k_final<<<BB*NN/4, 256>>>(x, c1b, c2b, resb, lng, lnb, out);
}